// round 13
// baseline (speedup 1.0000x reference)
#include <cuda_runtime.h>
#include <cuda_bf16.h>
#include <math.h>
#include <stdint.h>

typedef unsigned long long ull;

// ---------------------------------------------------------------------------
// Problem constants
// ---------------------------------------------------------------------------
#define TT        256
#define BB        128
#define TB        32768            // T*B
#define OBS_DIM   1604
#define SCALAR_D  452
#define HID       128
#define NACT      2305
#define CNN_FLAT  2560
#define CHUNK     4096
#define NCHUNK    8

// d_out layout (elements): logits | values | h_f | c_f
#define OUT_LOGITS 0L
#define OUT_VALUES 75530240L
#define OUT_HF     75563008L
#define OUT_CF     75579392L

// Scratch pool offsets (floats) — static
#define S_SC1     0L              // 32768 x 64
#define S_EMB     2097152L        // 32768 x 192
#define S_XW      8388608L        // 32768 x 512
#define S_OUTS    25165824L       // 32768 x 128
#define SCRATCH   29360128L       // ~117 MB

__device__ float g_sc[SCRATCH];
__device__ float g_c3[(long)CHUNK * CNN_FLAT];   // 4096 x 2560 (~42 MB)
__device__ float g_whh[512 * 128];               // normalized f32 w_hh
__device__ int   g_done[TB];
__device__ int   g_bf16;

// Prepped conv weights (f32; pair-interleaved ull layouts for f32x2)
__device__ float g_w1[576];
__device__ float g_b1[32];
__device__ float g_b2[64];
__device__ float g_b3[64];
__device__ float g_w2p[18432];   // (sl8, pr32, icl4, ky3, k3, o2)
__device__ float g_w3p[36864];   // (h2,  pr32, icl32, ky3, k3, o2)

// ---------------------------------------------------------------------------
// f32x2 packed-math helpers
// ---------------------------------------------------------------------------
__device__ __forceinline__ ull pk2(float a, float b)
{ ull r; asm("mov.b64 %0, {%1, %2};" : "=l"(r) : "f"(a), "f"(b)); return r; }
__device__ __forceinline__ float2 up2(ull v)
{ float2 f; asm("mov.b64 {%0, %1}, %2;" : "=f"(f.x), "=f"(f.y) : "l"(v)); return f; }
__device__ __forceinline__ ull bc2(float v)
{ ull r; asm("mov.b64 %0, {%1, %1};" : "=l"(r) : "f"(v)); return r; }
__device__ __forceinline__ void fma2(ull& d, ull a, ull b)
{ asm("fma.rn.f32x2 %0, %1, %2, %0;" : "+l"(d) : "l"(a), "l"(b)); }

// ---------------------------------------------------------------------------
// Clamped, dtype-dispatched input load
// ---------------------------------------------------------------------------
__device__ __forceinline__ float ldin(const void* p, long i, long n, int bf)
{
    if (n <= 0) return 0.f;
    if (i >= n) i = n - 1;
    if (i < 0) i = 0;
    return bf ? __bfloat162float(((const __nv_bfloat16*)p)[i])
              : ((const float*)p)[i];
}

// ---------------------------------------------------------------------------
// dtype sniffer (clamped scan)
// ---------------------------------------------------------------------------
__global__ void detect_kernel(const void* __restrict__ obs_raw, long obs_n)
{
    __shared__ int s_cnt;
    if (threadIdx.x == 0) s_cnt = 0;
    __syncthreads();
    long lim = obs_n / 2;
    if (lim > 4096) lim = 4096;
    const unsigned* w = (const unsigned*)obs_raw;
    int c = 0;
    for (long i = threadIdx.x; i < lim; i += blockDim.x) {
        unsigned b1 = (w[i] >> 8) & 0xFF;
        if (b1 >= 0x3A && b1 < 0x40) c++;
    }
    atomicAdd(&s_cnt, c);
    __syncthreads();
    if (threadIdx.x == 0) g_bf16 = (s_cnt > (int)(lim / 2)) ? 1 : 0;
}

// ---------------------------------------------------------------------------
// done_mask normalizer (clamped scan + clamped expansion)
// ---------------------------------------------------------------------------
__global__ void done_normalize_kernel(const void* __restrict__ raw, long done_n)
{
    __shared__ int s_ni, s_nf, s_nb;
    const unsigned* w = (const unsigned*)raw;
    int tid = threadIdx.x;
    if (tid == 0) { s_ni = 0; s_nf = 0; s_nb = 0; }
    __syncthreads();

    long scan = done_n / 4;
    if (scan > 8192) scan = 8192;
    int ni = 0, nf = 0, nb = 0;
    for (long i = tid; i < scan; i += blockDim.x) {
        unsigned v = w[i];
        if (v > 1u) ni = 1;
        if (v != 0u && v != 0x3F800000u) nf = 1;
        unsigned lo = v & 0xFFFFu, hi = v >> 16;
        if ((lo != 0u && lo != 0x3F80u) || (hi != 0u && hi != 0x3F80u)) nb = 1;
    }
    if (ni) atomicOr(&s_ni, 1);
    if (nf) atomicOr(&s_nf, 1);
    if (nb) atomicOr(&s_nb, 1);
    __syncthreads();

    long lim = done_n < TB ? done_n : TB;
    if (!s_ni) {
        const int* p = (const int*)raw;
        for (int i = tid; i < TB; i += blockDim.x)
            g_done[i] = (i < lim) ? (p[i] != 0) : 0;
    } else if (!s_nf) {
        const float* p = (const float*)raw;
        for (int i = tid; i < TB; i += blockDim.x)
            g_done[i] = (i < lim) ? (p[i] != 0.f) : 0;
    } else if (!s_nb) {
        const unsigned short* p = (const unsigned short*)raw;
        for (int i = tid; i < TB; i += blockDim.x)
            g_done[i] = (i < lim) ? (p[i] != 0) : 0;
    } else {
        const unsigned char* p = (const unsigned char*)raw;
        for (int i = tid; i < TB; i += blockDim.x)
            g_done[i] = (i < lim) ? (p[i] != 0) : 0;
    }
}

// ---------------------------------------------------------------------------
// w_hh normalizer
// ---------------------------------------------------------------------------
__global__ void whh_convert_kernel(const void* __restrict__ whh, long whh_n)
{
    int bf = g_bf16;
    for (int i = blockIdx.x * blockDim.x + threadIdx.x; i < 512 * 128;
         i += gridDim.x * blockDim.x)
        g_whh[i] = ldin(whh, i, whh_n, bf);
}

// ---------------------------------------------------------------------------
// Conv-weight prep (pair-interleaved layouts)
// g_w2p linear t (ull idx) = (((sl*32+pr)*4+icl)*3+ky)*3+k ; oc=pr*2+o, ic=sl*4+icl
// g_w3p linear t (ull idx) = (((h*32+pr)*32+icl)*3+ky)*3+k ; oc=pr*2+o, ic=h*32+icl
// ---------------------------------------------------------------------------
__global__ void weights_prep_kernel(
    const void* __restrict__ w1, long n1, const void* __restrict__ b1, long nb1,
    const void* __restrict__ w2, long n2, const void* __restrict__ b2, long nb2,
    const void* __restrict__ w3, long n3, const void* __restrict__ b3, long nb3)
{
    int bf = g_bf16;
    int stride = gridDim.x * blockDim.x;
    for (int j = blockIdx.x * blockDim.x + threadIdx.x; j < 36864; j += stride) {
        {   // w3p
            int o = j & 1; int t = j >> 1;
            int k = t % 3; t /= 3;
            int ky = t % 3; t /= 3;
            int icl = t & 31; t >>= 5;
            int pr = t & 31; int h = t >> 5;
            g_w3p[j] = ldin(w3, (long)(pr * 2 + o) * 576 + (h * 32 + icl) * 9 + ky * 3 + k, n3, bf);
        }
        if (j < 18432) {   // w2p
            int o = j & 1; int t = j >> 1;
            int k = t % 3; t /= 3;
            int ky = t % 3; t /= 3;
            int icl = t & 3; t >>= 2;
            int pr = t & 31; int sl = t >> 5;
            g_w2p[j] = ldin(w2, (long)(pr * 2 + o) * 288 + (sl * 4 + icl) * 9 + ky * 3 + k, n2, bf);
        }
        if (j < 576) g_w1[j] = ldin(w1, j, n1, bf);
        if (j < 32)  g_b1[j] = ldin(b1, j, nb1, bf);
        if (j < 64) { g_b2[j] = ldin(b2, j, nb2, bf); g_b3[j] = ldin(b3, j, nb3, bf); }
    }
}

// ---------------------------------------------------------------------------
// Output store: dtype-dispatched, clamped
// ---------------------------------------------------------------------------
__device__ __forceinline__ void store_out(void* out, long idx, long out_elems, float v)
{
    if (idx >= out_elems || idx < 0) return;
    if (g_bf16) ((__nv_bfloat16*)out)[idx] = __float2bfloat16(v);
    else        ((float*)out)[idx] = v;
}

// ---------------------------------------------------------------------------
// Fused CNN with duplicated-pair smem tiles (fma2 input = LDS.64, weight =
// pre-paired LDG.64 from L1; zero broadcast MOVs). Static smem 45,056 B.
//
// Phase1 (floats): IN @0 (2*34*22=1496, scalar, zero-padded borders)
//                  C1D @1496 (4 oc * 33 rows * 42 pitch = 5544, dup pairs)
//                  W1  @7040 (576)                          total 7616
// Phase2:          C2D @0 (32 ic * 16 rows * 22 pitch = 11264, dup pairs)
// ---------------------------------------------------------------------------
#define CV_IN   0
#define CV_C1D  1496
#define CV_W1   7040
#define CV_P1   7616
#define CV_C2D  0
#define CV_TOT  11264     // 45,056 B

__global__ void __launch_bounds__(256) conv_fused_kernel(
    const void* __restrict__ obs, long obs_n,
    float* __restrict__ c3out, int base)
{
    __shared__ __align__(16) float sm[CV_TOT];

    const int tid = threadIdx.x;
    const int bf  = g_bf16;
    const int s   = base + blockIdx.x;

    // zero phase-1 region (establishes all IN / C1D pads)
    for (int i = tid; i < CV_P1; i += 256) sm[i] = 0.f;
    __syncthreads();

    // fill IN (2x32x18, padded) + W1
    const long gbase = (long)s * OBS_DIM + SCALAR_D;
    for (int i = tid; i < 1152; i += 256) {
        int c = i / 576, r = i % 576;
        int y = r / 18, x = r % 18;
        sm[CV_IN + c * 748 + (y + 1) * 22 + (x + 1)] = ldin(obs, gbase + i, obs_n, bf);
    }
    for (int i = tid; i < 576; i += 256) sm[CV_W1 + i] = g_w1[i];

    // conv2 accumulators: thread = (ocg2 0..15 -> 2 oc pairs, y2 0..15)
    const int ocg2 = tid >> 4, y2 = tid & 15;
    ull acc2p[2][9];
    #pragma unroll
    for (int p = 0; p < 2; p++) {
        ull bz = pk2(g_b2[ocg2 * 4 + 2 * p], g_b2[ocg2 * 4 + 2 * p + 1]);
        #pragma unroll
        for (int x = 0; x < 9; x++) acc2p[p][x] = bz;
    }
    // conv1 mapping: thread = (ocl 0..3, y1 0..31, xh 0..1)
    const int ocl = tid >> 6, y1 = (tid >> 1) & 31, xh = tid & 1;
    __syncthreads();

    // ---- 8 slices of 4 conv1-oc: conv1 -> C1D(dup), conv2 partial ----
    for (int sl = 0; sl < 8; sl++) {
        // conv1: oc = sl*4 + ocl; outputs y1, x = xh*9 .. xh*9+8
        {
            int oc = sl * 4 + ocl;
            float acc[9];
            float bz = g_b1[oc];
            #pragma unroll
            for (int x = 0; x < 9; x++) acc[x] = bz;
            #pragma unroll
            for (int ic = 0; ic < 2; ic++) {
                #pragma unroll
                for (int ky = 0; ky < 3; ky++) {
                    const float* wp = sm + CV_W1 + (oc * 2 + ic) * 9 + ky * 3;
                    float w0 = wp[0], wA = wp[1], wB = wp[2];
                    const float* ip = sm + CV_IN + ic * 748 + (y1 + ky) * 22 + xh * 9;
                    float iv[11];
                    #pragma unroll
                    for (int q = 0; q < 11; q++) iv[q] = ip[q];
                    #pragma unroll
                    for (int x = 0; x < 9; x++)
                        acc[x] += w0 * iv[x] + wA * iv[x + 1] + wB * iv[x + 2];
                }
            }
            float* cp = sm + CV_C1D + ocl * 1386 + (y1 + 1) * 42;
            #pragma unroll
            for (int x = 0; x < 9; x++) {
                float v = fmaxf(acc[x], 0.f);
                *(float2*)(cp + 2 * (xh * 9 + x + 1)) = make_float2(v, v);
            }
        }
        __syncthreads();

        // conv2 partial over this slice's 4 channels
        #pragma unroll 1
        for (int icl = 0; icl < 4; icl++) {
            #pragma unroll
            for (int ky = 0; ky < 3; ky++) {
                const ull* dp = (const ull*)(sm + CV_C1D + icl * 1386 + (2 * y2 + ky) * 42);
                const ull* wp = (const ull*)g_w2p +
                                ((((long)sl * 32 + ocg2 * 2) * 4 + icl) * 3 + ky) * 3;
                ull w00 = wp[0],  w01 = wp[1],  w02 = wp[2];
                ull w10 = wp[36], w11 = wp[37], w12 = wp[38];
                ull d0 = dp[0];
                #pragma unroll
                for (int x = 0; x < 9; x++) {
                    ull d1 = dp[2 * x + 1], d2 = dp[2 * x + 2];
                    fma2(acc2p[0][x], w00, d0);
                    fma2(acc2p[0][x], w01, d1);
                    fma2(acc2p[0][x], w02, d2);
                    fma2(acc2p[1][x], w10, d0);
                    fma2(acc2p[1][x], w11, d1);
                    fma2(acc2p[1][x], w12, d2);
                    d0 = d2;
                }
            }
        }
        __syncthreads();
    }

    // ---- phase 2: zero C2D, then two oc-halves of (dup-write + conv3) ----
    for (int i = tid; i < CV_TOT; i += 256) sm[i] = 0.f;
    __syncthreads();

    const int ocg3 = tid >> 3, y3 = tid & 7;
    ull acc3p[5];
    {
        ull bz = pk2(g_b3[ocg3 * 2], g_b3[ocg3 * 2 + 1]);
        #pragma unroll
        for (int x = 0; x < 5; x++) acc3p[x] = bz;
    }

    #pragma unroll 1
    for (int h = 0; h < 2; h++) {
        // stage-write c2 dup for oc in [h*32, h*32+32): threads ocg2 in [h*8,h*8+8)
        if ((ocg2 >> 3) == h) {
            int iclb = ocg2 * 4 - h * 32;   // 0..28
            #pragma unroll
            for (int p = 0; p < 2; p++) {
                #pragma unroll
                for (int x = 0; x < 9; x++) {
                    float2 f = up2(acc2p[p][x]);
                    float v0 = fmaxf(f.x, 0.f), v1 = fmaxf(f.y, 0.f);
                    int off = y2 * 22 + 2 * (x + 1);
                    *(float2*)(sm + CV_C2D + (iclb + 2 * p)     * 352 + off) = make_float2(v0, v0);
                    *(float2*)(sm + CV_C2D + (iclb + 2 * p + 1) * 352 + off) = make_float2(v1, v1);
                }
            }
        }
        __syncthreads();

        // conv3 over this half's 32 channels (weights direct from L1)
        #pragma unroll 1
        for (int icl = 0; icl < 32; icl++) {
            #pragma unroll
            for (int ky = 0; ky < 3; ky++) {
                int row = 2 * y3 + ky - 1;
                const ull* wp = (const ull*)g_w3p +
                                ((((long)h * 32 + ocg3) * 32 + icl) * 3 + ky) * 3;
                ull w0 = wp[0], wA = wp[1], wB = wp[2];
                if (row >= 0 && row < 16) {
                    const ull* dp = (const ull*)(sm + CV_C2D + icl * 352 + row * 22);
                    ull d0 = dp[0];
                    #pragma unroll
                    for (int x = 0; x < 5; x++) {
                        ull d1 = dp[2 * x + 1], d2 = dp[2 * x + 2];
                        fma2(acc3p[x], w0, d0);
                        fma2(acc3p[x], wA, d1);
                        fma2(acc3p[x], wB, d2);
                        d0 = d2;
                    }
                }
            }
        }
        __syncthreads();
    }

    float* outp = c3out + (long)blockIdx.x * CNN_FLAT;
    #pragma unroll
    for (int x = 0; x < 5; x++) {
        float2 f = up2(acc3p[x]);
        outp[(long)(ocg3 * 2 + 0) * 40 + y3 * 5 + x] = fmaxf(f.x, 0.f);
        outp[(long)(ocg3 * 2 + 1) * 40 + y3 * 5 + x] = fmaxf(f.y, 0.f);
    }
}

// ---------------------------------------------------------------------------
// Tiled SGEMM with f32x2 microkernel (unchanged from passing R11)
// ---------------------------------------------------------------------------
template <bool RELU, bool TO_OUT>
__global__ void __launch_bounds__(256, 2) gemm_bt_kernel(
    const void* __restrict__ Araw, long a_n,
    const float* __restrict__ Af, long lda,
    const void* __restrict__ B, long b_n,
    const void* __restrict__ bias, long bias_n,
    const void* __restrict__ bias2, long bias2_n,
    float* __restrict__ Cf, long c_off, long ldc, int N, int K,
    void* outbuf, long out_elems)
{
    __shared__ __align__(16) float sA[16][68];
    __shared__ __align__(16) float sB[16][68];

    const int tid = threadIdx.x;
    const int tx = tid & 15, ty = tid >> 4;
    const int m0 = blockIdx.x * 64;
    const int n0 = blockIdx.y * 64;
    const int bf = g_bf16;

    ull accp[4][2] = {};

    for (int k0 = 0; k0 < K; k0 += 16) {
        for (int e = tid; e < 1024; e += 256) {
            int k = e & 15, m = e >> 4;
            int gk = k0 + k;
            float v = 0.f;
            if (gk < K) {
                long ai = (long)(m0 + m) * lda + gk;
                v = Af ? Af[ai] : ldin(Araw, ai, a_n, bf);
            }
            sA[k][m] = v;
        }
        for (int e = tid; e < 1024; e += 256) {
            int k = e & 15, n = e >> 4;
            int gn = n0 + n, gk = k0 + k;
            sB[k][n] = (gn < N && gk < K) ? ldin(B, (long)gn * K + gk, b_n, bf) : 0.f;
        }
        __syncthreads();
        #pragma unroll
        for (int kk = 0; kk < 16; kk++) {
            float4 av = *(const float4*)&sA[kk][ty * 4];
            ull b0 = *(const ull*)&sB[kk][tx * 4];
            ull b1 = *(const ull*)&sB[kk][tx * 4 + 2];
            ull a0 = bc2(av.x), a1 = bc2(av.y), a2 = bc2(av.z), a3 = bc2(av.w);
            fma2(accp[0][0], a0, b0); fma2(accp[0][1], a0, b1);
            fma2(accp[1][0], a1, b0); fma2(accp[1][1], a1, b1);
            fma2(accp[2][0], a2, b0); fma2(accp[2][1], a2, b1);
            fma2(accp[3][0], a3, b0); fma2(accp[3][1], a3, b1);
        }
        __syncthreads();
    }

    #pragma unroll
    for (int i = 0; i < 4; i++) {
        int gm = m0 + ty * 4 + i;
        #pragma unroll
        for (int jp = 0; jp < 2; jp++) {
            float2 f = up2(accp[i][jp]);
            #pragma unroll
            for (int o = 0; o < 2; o++) {
                int gn = n0 + tx * 4 + jp * 2 + o;
                if (gn < N) {
                    float v = o ? f.y : f.x;
                    if (bias)  v += ldin(bias,  gn, bias_n,  bf);
                    if (bias2) v += ldin(bias2, gn, bias2_n, bf);
                    if (RELU) v = fmaxf(v, 0.f);
                    if (TO_OUT) store_out(outbuf, c_off + (long)gm * ldc + gn, out_elems, v);
                    else        Cf[(long)gm * ldc + gn] = v;
                }
            }
        }
    }
}

// ---------------------------------------------------------------------------
// LSTM (unchanged from passing R11)
// ---------------------------------------------------------------------------
#define LW_SM_W2   0
#define LW_SM_H    11264
#define LW_SM_G    11392
#define LW_SM_TOT  11904

__global__ void __launch_bounds__(512) lstm_kernel(
    const void* __restrict__ h0, long h0_n,
    const void* __restrict__ c0, long c0_n,
    void* outbuf, long out_elems)
{
    __shared__ float sm[LW_SM_TOT];
    float* s_w2t = sm + LW_SM_W2;
    float* s_h   = sm + LW_SM_H;
    float* s_g   = sm + LW_SM_G;

    const int b = blockIdx.x;
    const int r = threadIdx.x;
    const int bf = g_bf16;

    const float* xw   = g_sc + S_XW;
    float*       outs = g_sc + S_OUTS;

    float wreg[64];
    #pragma unroll
    for (int k = 0; k < 64; k++) wreg[k] = g_whh[r * 128 + k];
    #pragma unroll
    for (int k = 0; k < 22; k++) s_w2t[k * 512 + r] = g_whh[r * 128 + 64 + k];

    float c = 0.f;
    if (r < 128) {
        s_h[r] = ldin(h0, (long)b * 128 + r, h0_n, bf);
        c      = ldin(c0, (long)b * 128 + r, c0_n, bf);
    }
    __syncthreads();

    for (int t = 0; t < TT; t++) {
        if (r < 128) {
            float keep = (t == 0) ? 1.f : (g_done[(t - 1) * BB + b] ? 0.f : 1.f);
            s_h[r] *= keep;
            c *= keep;
        }
        __syncthreads();

        float acc = xw[((long)t * BB + b) * 512 + r];
        #pragma unroll
        for (int k = 0; k < 64; k += 4) {
            float4 h4 = *(const float4*)&s_h[k];
            acc += wreg[k] * h4.x + wreg[k + 1] * h4.y
                 + wreg[k + 2] * h4.z + wreg[k + 3] * h4.w;
        }
        #pragma unroll
        for (int k = 0; k < 22; k++)
            acc += s_w2t[k * 512 + r] * s_h[64 + k];
        const float* wg = g_whh + r * 128 + 86;
        #pragma unroll
        for (int k = 0; k < 42; k++)
            acc += wg[k] * s_h[86 + k];
        s_g[r] = acc;
        __syncthreads();

        if (r < 128) {
            float ig = 1.f / (1.f + expf(-s_g[r]));
            float fg = 1.f / (1.f + expf(-s_g[128 + r]));
            float gg = tanhf(s_g[256 + r]);
            float og = 1.f / (1.f + expf(-s_g[384 + r]));
            c = fg * c + ig * gg;
            float h = og * tanhf(c);
            s_h[r] = h;
            outs[((long)t * BB + b) * 128 + r] = h;
        }
        __syncthreads();
    }

    if (r < 128) {
        store_out(outbuf, OUT_HF + (long)b * 128 + r, out_elems, s_h[r]);
        store_out(outbuf, OUT_CF + (long)b * 128 + r, out_elems, c);
    }
}

// ---------------------------------------------------------------------------
// Value head: one warp per sample
// ---------------------------------------------------------------------------
__global__ void value_kernel(const void* __restrict__ vw, long vw_n,
                             const void* __restrict__ vb, long vb_n,
                             void* outbuf, long out_elems)
{
    int gw   = (blockIdx.x * blockDim.x + threadIdx.x) >> 5;
    int lane = threadIdx.x & 31;
    if (gw >= TB) return;
    const int bf = g_bf16;
    const float* h = g_sc + S_OUTS + (long)gw * 128;
    float s = 0.f;
    #pragma unroll
    for (int k = lane; k < 128; k += 32) s += h[k] * ldin(vw, k, vw_n, bf);
    #pragma unroll
    for (int off = 16; off; off >>= 1) s += __shfl_xor_sync(0xffffffffu, s, off);
    if (lane == 0)
        store_out(outbuf, OUT_VALUES + gw, out_elems, s + ldin(vb, 0, vb_n, bf));
}

// ---------------------------------------------------------------------------
// Host launcher — static smem only, no cudaFuncSetAttribute anywhere.
// ---------------------------------------------------------------------------
extern "C" void kernel_launch(void* const* d_in, const int* in_sizes, int n_in,
                              void* d_out, int out_size)
{
    static const long WANT[24] = {
        52559872L, 16384L, 16384L, 32768L,
        576L, 32L, 18432L, 64L, 36864L, 64L,
        327680L, 128L, 28928L, 64L, 4096L, 64L,
        98304L, 65536L, 512L, 512L,
        295040L, 2305L, 128L, 1L
    };
    const void* inp[24];
    long        bnd[24];
    {
        int matched = 0;
        static const long SCALES[3] = {1L, 4L, 2L};
        for (int si = 0; si < 3 && !matched; si++) {
            long sc = SCALES[si];
            int used[64] = {0};
            int ok = (n_in >= 24);
            const void* tp[24]; long tb[24];
            if (ok) {
                for (int j = 0; j < 24; j++) {
                    int found = -1;
                    for (int i = 0; i < n_in && i < 64; i++) {
                        if (!used[i] && (long)in_sizes[i] == WANT[j] * sc) { found = i; break; }
                    }
                    if (found < 0) { ok = 0; break; }
                    used[found] = 1;
                    tp[j] = d_in[found];
                    long actual = (long)in_sizes[found];
                    tb[j] = (WANT[j] < actual) ? WANT[j] : actual;
                }
            }
            if (ok) {
                for (int j = 0; j < 24; j++) { inp[j] = tp[j]; bnd[j] = tb[j]; }
                matched = 1;
            }
        }
        if (!matched) {
            for (int j = 0; j < 24; j++) {
                if (j < n_in) {
                    inp[j] = d_in[j];
                    long actual = (long)in_sizes[j];
                    bnd[j] = (WANT[j] < actual) ? WANT[j] : actual;
                } else {
                    inp[j] = d_in[0];
                    bnd[j] = 0;
                }
            }
        }
    }

    const long out_elems = (long)out_size;

    float *scP, *c3P;
    cudaGetSymbolAddress((void**)&scP, g_sc);
    cudaGetSymbolAddress((void**)&c3P, g_c3);

    // 1) dtype sniff + normalizers + weight prep
    detect_kernel<<<1, 256>>>(inp[0], bnd[0]);
    done_normalize_kernel<<<1, 1024>>>(inp[3], bnd[3]);
    whh_convert_kernel<<<64, 256>>>(inp[17], bnd[17]);
    weights_prep_kernel<<<64, 256>>>(
        inp[4], bnd[4], inp[5], bnd[5],
        inp[6], bnd[6], inp[7], bnd[7],
        inp[8], bnd[8], inp[9], bnd[9]);

    // 2) chunked CNN + fc GEMM -> emb cols 0..127
    for (int ch = 0; ch < NCHUNK; ch++) {
        int base = ch * CHUNK;
        conv_fused_kernel<<<CHUNK, 256>>>(inp[0], bnd[0], c3P, base);
        gemm_bt_kernel<true, false><<<dim3(CHUNK / 64, 2), 256>>>(
            nullptr, 0L, c3P, CNN_FLAT,
            inp[10], bnd[10], inp[11], bnd[11], nullptr, 0L,
            scP + S_EMB + (long)base * 192, 0L, 192, 128, CNN_FLAT,
            d_out, out_elems);
    }

    // 3) Scalar MLP -> emb cols 128..191
    gemm_bt_kernel<true, false><<<dim3(TB / 64, 1), 256>>>(
        inp[0], bnd[0], nullptr, OBS_DIM,
        inp[12], bnd[12], inp[13], bnd[13], nullptr, 0L,
        scP + S_SC1, 0L, 64, 64, SCALAR_D, d_out, out_elems);
    gemm_bt_kernel<true, false><<<dim3(TB / 64, 1), 256>>>(
        nullptr, 0L, scP + S_SC1, 64,
        inp[14], bnd[14], inp[15], bnd[15], nullptr, 0L,
        scP + S_EMB + 128, 0L, 192, 64, 64, d_out, out_elems);

    // 4) LSTM input projection
    gemm_bt_kernel<false, false><<<dim3(TB / 64, 8), 256>>>(
        nullptr, 0L, scP + S_EMB, 192,
        inp[16], bnd[16], inp[18], bnd[18], inp[19], bnd[19],
        scP + S_XW, 0L, 512, 512, 192, d_out, out_elems);

    // 5) Recurrence
    lstm_kernel<<<BB, 512>>>(inp[1], bnd[1], inp[2], bnd[2], d_out, out_elems);

    // 6) Policy head -> logits
    gemm_bt_kernel<false, true><<<dim3(TB / 64, (NACT + 63) / 64), 256>>>(
        nullptr, 0L, scP + S_OUTS, 128,
        inp[20], bnd[20], inp[21], bnd[21], nullptr, 0L,
        nullptr, OUT_LOGITS, NACT, NACT, 128, d_out, out_elems);

    // 7) Value head -> values
    value_kernel<<<TB / 8, 256>>>(inp[22], bnd[22], inp[23], bnd[23],
                                  d_out, out_elems);
}

// round 14
// speedup vs baseline: 1.3757x; 1.3757x over previous
#include <cuda_runtime.h>
#include <cuda_bf16.h>
#include <math.h>
#include <stdint.h>

typedef unsigned long long ull;

// ---------------------------------------------------------------------------
// Problem constants
// ---------------------------------------------------------------------------
#define TT        256
#define BB        128
#define TB        32768            // T*B
#define OBS_DIM   1604
#define SCALAR_D  452
#define HID       128
#define NACT      2305
#define CNN_FLAT  2560
#define CHUNK     4096
#define NCHUNK    8

// d_out layout (elements): logits | values | h_f | c_f
#define OUT_LOGITS 0L
#define OUT_VALUES 75530240L
#define OUT_HF     75563008L
#define OUT_CF     75579392L

// Scratch pool offsets (floats) — static
#define S_SC1     0L              // 32768 x 64
#define S_EMB     2097152L        // 32768 x 192
#define S_XW      8388608L        // 32768 x 512
#define S_OUTS    25165824L       // 32768 x 128
#define SCRATCH   29360128L       // ~117 MB

__device__ float g_sc[SCRATCH];
__device__ float g_c3[(long)CHUNK * CNN_FLAT];   // 4096 x 2560 (~42 MB)
__device__ float g_whh[512 * 128];               // normalized f32 w_hh
__device__ int   g_done[TB];
__device__ int   g_bf16;

// Prepped conv weights (f32; pair-interleaved ull layouts for f32x2)
__device__ float g_w1[576];
__device__ float g_b1[32];
__device__ float g_b2[64];
__device__ float g_b3[64];
__device__ float g_w2p[18432];   // (ib4, pr32, icl8, ky3, k3, o2)
__device__ float g_w3p[36864];   // (ib32, pr32, icl2, ky3, k3, o2)

// ---------------------------------------------------------------------------
// f32x2 packed-math helpers
// ---------------------------------------------------------------------------
__device__ __forceinline__ ull pk2(float a, float b)
{ ull r; asm("mov.b64 %0, {%1, %2};" : "=l"(r) : "f"(a), "f"(b)); return r; }
__device__ __forceinline__ float2 up2(ull v)
{ float2 f; asm("mov.b64 {%0, %1}, %2;" : "=f"(f.x), "=f"(f.y) : "l"(v)); return f; }
__device__ __forceinline__ ull bc2(float v)
{ ull r; asm("mov.b64 %0, {%1, %1};" : "=l"(r) : "f"(v)); return r; }
__device__ __forceinline__ void fma2(ull& d, ull a, ull b)
{ asm("fma.rn.f32x2 %0, %1, %2, %0;" : "+l"(d) : "l"(a), "l"(b)); }

// ---------------------------------------------------------------------------
// Clamped, dtype-dispatched input load
// ---------------------------------------------------------------------------
__device__ __forceinline__ float ldin(const void* p, long i, long n, int bf)
{
    if (n <= 0) return 0.f;
    if (i >= n) i = n - 1;
    if (i < 0) i = 0;
    return bf ? __bfloat162float(((const __nv_bfloat16*)p)[i])
              : ((const float*)p)[i];
}

// ---------------------------------------------------------------------------
// MERGED prep kernel (single launch). Every block independently re-derives
// the dtype flag from the same clamped 4096-word scan of obs (deterministic,
// identical result per block -> no cross-block dependency), then performs its
// role:  block 0: g_bf16 store + done-mask normalize
//        blocks 1..16: w_hh -> f32
//        blocks 17..63: conv weight prep (pair-interleave)
// ---------------------------------------------------------------------------
__global__ void __launch_bounds__(256) prep_kernel(
    const void* __restrict__ obs, long obs_n,
    const void* __restrict__ done, long done_n,
    const void* __restrict__ whh, long whh_n,
    const void* __restrict__ w1, long n1, const void* __restrict__ b1, long nb1,
    const void* __restrict__ w2, long n2, const void* __restrict__ b2, long nb2,
    const void* __restrict__ w3, long n3, const void* __restrict__ b3, long nb3)
{
    __shared__ int s_cnt;
    const int tid = threadIdx.x;
    const int bid = blockIdx.x;

    // --- per-block dtype detection (clamped scan, identical in all blocks) ---
    if (tid == 0) s_cnt = 0;
    __syncthreads();
    long lim = obs_n / 2;
    if (lim > 4096) lim = 4096;
    {
        const unsigned* w = (const unsigned*)obs;
        int c = 0;
        for (long i = tid; i < lim; i += 256) {
            unsigned b1v = (w[i] >> 8) & 0xFF;
            if (b1v >= 0x3A && b1v < 0x40) c++;
        }
        atomicAdd(&s_cnt, c);
    }
    __syncthreads();
    const int bf = (s_cnt > (int)(lim / 2)) ? 1 : 0;

    if (bid == 0) {
        if (tid == 0) g_bf16 = bf;
        // --- done-mask normalize (clamped scan + clamped expansion) ---
        __shared__ int s_ni, s_nf, s_nb;
        if (tid == 0) { s_ni = 0; s_nf = 0; s_nb = 0; }
        __syncthreads();
        long scan = done_n / 4;
        if (scan > 8192) scan = 8192;
        const unsigned* w = (const unsigned*)done;
        int ni = 0, nf = 0, nb = 0;
        for (long i = tid; i < scan; i += 256) {
            unsigned v = w[i];
            if (v > 1u) ni = 1;
            if (v != 0u && v != 0x3F800000u) nf = 1;
            unsigned lo = v & 0xFFFFu, hi = v >> 16;
            if ((lo != 0u && lo != 0x3F80u) || (hi != 0u && hi != 0x3F80u)) nb = 1;
        }
        if (ni) atomicOr(&s_ni, 1);
        if (nf) atomicOr(&s_nf, 1);
        if (nb) atomicOr(&s_nb, 1);
        __syncthreads();
        long dl = done_n < TB ? done_n : TB;
        if (!s_ni) {
            const int* p = (const int*)done;
            for (int i = tid; i < TB; i += 256) g_done[i] = (i < dl) ? (p[i] != 0) : 0;
        } else if (!s_nf) {
            const float* p = (const float*)done;
            for (int i = tid; i < TB; i += 256) g_done[i] = (i < dl) ? (p[i] != 0.f) : 0;
        } else if (!s_nb) {
            const unsigned short* p = (const unsigned short*)done;
            for (int i = tid; i < TB; i += 256) g_done[i] = (i < dl) ? (p[i] != 0) : 0;
        } else {
            const unsigned char* p = (const unsigned char*)done;
            for (int i = tid; i < TB; i += 256) g_done[i] = (i < dl) ? (p[i] != 0) : 0;
        }
    } else if (bid <= 16) {
        // --- w_hh normalize: 16 blocks cover 65536 elements ---
        for (int i = (bid - 1) * 256 + tid; i < 512 * 128; i += 16 * 256)
            g_whh[i] = ldin(whh, i, whh_n, bf);
    } else {
        // --- conv weight prep: 47 blocks cover 36864 ---
        for (int j = (bid - 17) * 256 + tid; j < 36864; j += 47 * 256) {
            {   // w3p: (ib32, pr32, icl2, ky3, k3, o2)
                int o = j & 1; int t = j >> 1;
                int k = t % 3; t /= 3;
                int ky = t % 3; t /= 3;
                int icl = t & 1; t >>= 1;
                int pr = t & 31; int ib = t >> 5;
                g_w3p[j] = ldin(w3, (long)(pr * 2 + o) * 576 + (ib * 2 + icl) * 9 + ky * 3 + k, n3, bf);
            }
            if (j < 18432) {   // w2p: (ib4, pr32, icl8, ky3, k3, o2)
                int o = j & 1; int t = j >> 1;
                int k = t % 3; t /= 3;
                int ky = t % 3; t /= 3;
                int icl = t & 7; t >>= 3;
                int pr = t & 31; int ib = t >> 5;
                g_w2p[j] = ldin(w2, (long)(pr * 2 + o) * 288 + (ib * 8 + icl) * 9 + ky * 3 + k, n2, bf);
            }
            if (j < 576) g_w1[j] = ldin(w1, j, n1, bf);
            if (j < 32)  g_b1[j] = ldin(b1, j, nb1, bf);
            if (j < 64) { g_b2[j] = ldin(b2, j, nb2, bf); g_b3[j] = ldin(b3, j, nb3, bf); }
        }
    }
}

// ---------------------------------------------------------------------------
// Output store: dtype-dispatched, clamped
// ---------------------------------------------------------------------------
__device__ __forceinline__ void store_out(void* out, long idx, long out_elems, float v)
{
    if (idx >= out_elems || idx < 0) return;
    if (g_bf16) ((__nv_bfloat16*)out)[idx] = __float2bfloat16(v);
    else        ((float*)out)[idx] = v;
}

// ---------------------------------------------------------------------------
// Fused CNN (R11-proven structure; conv3 de-staged: weights straight from
// L1-resident g_w3p, NO barriers in the conv3 loop). Static smem 48,224 B.
// Phase1 (floats): IN @0 (2*34*22=1496) | C1 @1496 (8*33*22=5808)
//                  | W2 @7304 (4608) | W1 @11912 (144)    -> 12056 total
// Phase2:          C2 @0 (64*16*10=10240, scalar)
// ---------------------------------------------------------------------------
#define CV_IN   0
#define CV_C1   1496
#define CV_W2   7304
#define CV_W1   11912
#define CV_C2   0
#define CV_TOT  12056

__global__ void __launch_bounds__(256) conv_fused_kernel(
    const void* __restrict__ obs, long obs_n,
    float* __restrict__ c3out, int base)
{
    __shared__ __align__(16) float sm[CV_TOT];

    const int tid = threadIdx.x;
    const int bf  = g_bf16;
    const int s   = base + blockIdx.x;

    // zero IN + C1 (padding borders persist across ib slices)
    for (int i = tid; i < CV_W2; i += 256) sm[i] = 0.f;
    __syncthreads();

    // obs grid -> padded IN
    const long gbase = (long)s * OBS_DIM + SCALAR_D;
    for (int i = tid; i < 1152; i += 256) {
        int c = i / 576, r = i % 576;
        int y = r / 18, x = r % 18;
        sm[CV_IN + c * 748 + (y + 1) * 22 + (x + 1)] = ldin(obs, gbase + i, obs_n, bf);
    }

    // conv2 accumulators: thread = (ocg2 0..15 -> 2 oc pairs, y2 0..15)
    const int ocg2 = tid >> 4, y2 = tid & 15;
    ull acc2p[2][9];
    #pragma unroll
    for (int p = 0; p < 2; p++) {
        ull bz = pk2(g_b2[ocg2 * 4 + 2 * p], g_b2[ocg2 * 4 + 2 * p + 1]);
        #pragma unroll
        for (int x = 0; x < 9; x++) acc2p[p][x] = bz;
    }
    const int ocl = tid >> 5, y1 = tid & 31;

    // ---- conv1 (8 oc at a time) + conv2 partial accumulation ----
    for (int ib = 0; ib < 4; ib++) {
        for (int i = tid; i < 144; i += 256) sm[CV_W1 + i] = g_w1[ib * 144 + i];
        for (int i = tid; i < 1152; i += 256)
            ((float4*)(sm + CV_W2))[i] = ((const float4*)(g_w2p + ib * 4608))[i];
        __syncthreads();

        // conv1: one (ocl, y1) per thread, 18 x-outputs
        {
            float acc[18];
            float bz = g_b1[ib * 8 + ocl];
            #pragma unroll
            for (int x = 0; x < 18; x++) acc[x] = bz;
            #pragma unroll
            for (int ic = 0; ic < 2; ic++) {
                #pragma unroll
                for (int ky = 0; ky < 3; ky++) {
                    const float2* ip2 = (const float2*)(sm + CV_IN + ic * 748 + (y1 + ky) * 22);
                    float in[20];
                    #pragma unroll
                    for (int q = 0; q < 10; q++) {
                        float2 t = ip2[q]; in[2 * q] = t.x; in[2 * q + 1] = t.y;
                    }
                    const float* wp = sm + CV_W1 + (ocl * 2 + ic) * 9 + ky * 3;
                    float w0 = wp[0], wA = wp[1], wB = wp[2];
                    #pragma unroll
                    for (int x = 0; x < 18; x++)
                        acc[x] += w0 * in[x] + wA * in[x + 1] + wB * in[x + 2];
                }
            }
            #pragma unroll
            for (int x = 0; x < 18; x++)
                sm[CV_C1 + ocl * 726 + (y1 + 1) * 22 + (x + 1)] = fmaxf(acc[x], 0.f);
        }
        __syncthreads();

        // conv2 partial over this 8-ic slice (f32x2, oc pairs)
        #pragma unroll 1
        for (int icl = 0; icl < 8; icl++) {
            #pragma unroll
            for (int ky = 0; ky < 3; ky++) {
                const float2* ip2 = (const float2*)(sm + CV_C1 + icl * 726 + (2 * y2 + ky) * 22);
                float in[20];
                #pragma unroll
                for (int q = 0; q < 10; q++) {
                    float2 t = ip2[q]; in[2 * q] = t.x; in[2 * q + 1] = t.y;
                }
                const ull* wp = (const ull*)(sm + CV_W2);
                ull w[2][3];
                #pragma unroll
                for (int p = 0; p < 2; p++) {
                    int wb = (((ocg2 * 2 + p) * 8 + icl) * 3 + ky) * 3;
                    w[p][0] = wp[wb]; w[p][1] = wp[wb + 1]; w[p][2] = wp[wb + 2];
                }
                #pragma unroll
                for (int x = 0; x < 9; x++) {
                    ull b0 = bc2(in[2 * x]);
                    ull b1v = bc2(in[2 * x + 1]);
                    ull b2v = bc2(in[2 * x + 2]);
                    fma2(acc2p[0][x], w[0][0], b0);
                    fma2(acc2p[0][x], w[0][1], b1v);
                    fma2(acc2p[0][x], w[0][2], b2v);
                    fma2(acc2p[1][x], w[1][0], b0);
                    fma2(acc2p[1][x], w[1][1], b1v);
                    fma2(acc2p[1][x], w[1][2], b2v);
                }
            }
        }
        __syncthreads();
    }

    // write c2 (ReLU, unpadded 64x16x9, pitch 10) over the phase-1 region
    #pragma unroll
    for (int p = 0; p < 2; p++)
        #pragma unroll
        for (int x = 0; x < 9; x++) {
            float2 f = up2(acc2p[p][x]);
            sm[CV_C2 + (ocg2 * 4 + 2 * p + 0) * 160 + y2 * 10 + x] = fmaxf(f.x, 0.f);
            sm[CV_C2 + (ocg2 * 4 + 2 * p + 1) * 160 + y2 * 10 + x] = fmaxf(f.y, 0.f);
        }
    __syncthreads();

    // ---- conv3: thread = (ocg3 0..31 -> 1 oc pair, y3 0..7) ----
    // Weights read DIRECTLY from g_w3p (L1-resident, ~9 KB/half); no barriers.
    const int ocg3 = tid >> 3, y3 = tid & 7;
    ull acc3p[5];
    {
        ull bz = pk2(g_b3[ocg3 * 2], g_b3[ocg3 * 2 + 1]);
        #pragma unroll
        for (int x = 0; x < 5; x++) acc3p[x] = bz;
    }

    #pragma unroll 1
    for (int ib = 0; ib < 32; ib++) {
        #pragma unroll
        for (int icl = 0; icl < 2; icl++) {
            int ic = ib * 2 + icl;
            #pragma unroll
            for (int ky = 0; ky < 3; ky++) {
                int row = 2 * y3 + ky - 1;
                const ull* wp = (const ull*)g_w3p +
                                (((long)(ib * 32 + ocg3) * 2 + icl) * 3 + ky) * 3;
                ull w0 = wp[0], wA = wp[1], wB = wp[2];
                float in[11];
                if (row >= 0 && row < 16) {
                    const float2* cp2 = (const float2*)(sm + CV_C2 + ic * 160 + row * 10);
                    float2 t0 = cp2[0], t1 = cp2[1], t2 = cp2[2], t3 = cp2[3], t4 = cp2[4];
                    in[0] = 0.f;
                    in[1] = t0.x; in[2] = t0.y; in[3] = t1.x; in[4] = t1.y;
                    in[5] = t2.x; in[6] = t2.y; in[7] = t3.x; in[8] = t3.y;
                    in[9] = t4.x; in[10] = 0.f;
                } else {
                    #pragma unroll
                    for (int q = 0; q < 11; q++) in[q] = 0.f;
                }
                #pragma unroll
                for (int x = 0; x < 5; x++) {
                    fma2(acc3p[x], w0, bc2(in[2 * x]));
                    fma2(acc3p[x], wA, bc2(in[2 * x + 1]));
                    fma2(acc3p[x], wB, bc2(in[2 * x + 2]));
                }
            }
        }
    }

    float* outp = c3out + (long)blockIdx.x * CNN_FLAT;
    #pragma unroll
    for (int x = 0; x < 5; x++) {
        float2 f = up2(acc3p[x]);
        outp[(long)(ocg3 * 2 + 0) * 40 + y3 * 5 + x] = fmaxf(f.x, 0.f);
        outp[(long)(ocg3 * 2 + 1) * 40 + y3 * 5 + x] = fmaxf(f.y, 0.f);
    }
}

// ---------------------------------------------------------------------------
// Tiled SGEMM with f32x2 microkernel (unchanged from passing R11)
// ---------------------------------------------------------------------------
template <bool RELU, bool TO_OUT>
__global__ void __launch_bounds__(256, 2) gemm_bt_kernel(
    const void* __restrict__ Araw, long a_n,
    const float* __restrict__ Af, long lda,
    const void* __restrict__ B, long b_n,
    const void* __restrict__ bias, long bias_n,
    const void* __restrict__ bias2, long bias2_n,
    float* __restrict__ Cf, long c_off, long ldc, int N, int K,
    void* outbuf, long out_elems)
{
    __shared__ __align__(16) float sA[16][68];
    __shared__ __align__(16) float sB[16][68];

    const int tid = threadIdx.x;
    const int tx = tid & 15, ty = tid >> 4;
    const int m0 = blockIdx.x * 64;
    const int n0 = blockIdx.y * 64;
    const int bf = g_bf16;

    ull accp[4][2] = {};

    for (int k0 = 0; k0 < K; k0 += 16) {
        for (int e = tid; e < 1024; e += 256) {
            int k = e & 15, m = e >> 4;
            int gk = k0 + k;
            float v = 0.f;
            if (gk < K) {
                long ai = (long)(m0 + m) * lda + gk;
                v = Af ? Af[ai] : ldin(Araw, ai, a_n, bf);
            }
            sA[k][m] = v;
        }
        for (int e = tid; e < 1024; e += 256) {
            int k = e & 15, n = e >> 4;
            int gn = n0 + n, gk = k0 + k;
            sB[k][n] = (gn < N && gk < K) ? ldin(B, (long)gn * K + gk, b_n, bf) : 0.f;
        }
        __syncthreads();
        #pragma unroll
        for (int kk = 0; kk < 16; kk++) {
            float4 av = *(const float4*)&sA[kk][ty * 4];
            ull b0 = *(const ull*)&sB[kk][tx * 4];
            ull b1 = *(const ull*)&sB[kk][tx * 4 + 2];
            ull a0 = bc2(av.x), a1 = bc2(av.y), a2 = bc2(av.z), a3 = bc2(av.w);
            fma2(accp[0][0], a0, b0); fma2(accp[0][1], a0, b1);
            fma2(accp[1][0], a1, b0); fma2(accp[1][1], a1, b1);
            fma2(accp[2][0], a2, b0); fma2(accp[2][1], a2, b1);
            fma2(accp[3][0], a3, b0); fma2(accp[3][1], a3, b1);
        }
        __syncthreads();
    }

    #pragma unroll
    for (int i = 0; i < 4; i++) {
        int gm = m0 + ty * 4 + i;
        #pragma unroll
        for (int jp = 0; jp < 2; jp++) {
            float2 f = up2(accp[i][jp]);
            #pragma unroll
            for (int o = 0; o < 2; o++) {
                int gn = n0 + tx * 4 + jp * 2 + o;
                if (gn < N) {
                    float v = o ? f.y : f.x;
                    if (bias)  v += ldin(bias,  gn, bias_n,  bf);
                    if (bias2) v += ldin(bias2, gn, bias2_n, bf);
                    if (RELU) v = fmaxf(v, 0.f);
                    if (TO_OUT) store_out(outbuf, c_off + (long)gm * ldc + gn, out_elems, v);
                    else        Cf[(long)gm * ldc + gn] = v;
                }
            }
        }
    }
}

// ---------------------------------------------------------------------------
// LSTM (unchanged from passing R11)
// ---------------------------------------------------------------------------
#define LW_SM_W2   0
#define LW_SM_H    11264
#define LW_SM_G    11392
#define LW_SM_TOT  11904

__global__ void __launch_bounds__(512) lstm_kernel(
    const void* __restrict__ h0, long h0_n,
    const void* __restrict__ c0, long c0_n,
    void* outbuf, long out_elems)
{
    __shared__ float sm[LW_SM_TOT];
    float* s_w2t = sm + LW_SM_W2;
    float* s_h   = sm + LW_SM_H;
    float* s_g   = sm + LW_SM_G;

    const int b = blockIdx.x;
    const int r = threadIdx.x;
    const int bf = g_bf16;

    const float* xw   = g_sc + S_XW;
    float*       outs = g_sc + S_OUTS;

    float wreg[64];
    #pragma unroll
    for (int k = 0; k < 64; k++) wreg[k] = g_whh[r * 128 + k];
    #pragma unroll
    for (int k = 0; k < 22; k++) s_w2t[k * 512 + r] = g_whh[r * 128 + 64 + k];

    float c = 0.f;
    if (r < 128) {
        s_h[r] = ldin(h0, (long)b * 128 + r, h0_n, bf);
        c      = ldin(c0, (long)b * 128 + r, c0_n, bf);
    }
    __syncthreads();

    for (int t = 0; t < TT; t++) {
        if (r < 128) {
            float keep = (t == 0) ? 1.f : (g_done[(t - 1) * BB + b] ? 0.f : 1.f);
            s_h[r] *= keep;
            c *= keep;
        }
        __syncthreads();

        float acc = xw[((long)t * BB + b) * 512 + r];
        #pragma unroll
        for (int k = 0; k < 64; k += 4) {
            float4 h4 = *(const float4*)&s_h[k];
            acc += wreg[k] * h4.x + wreg[k + 1] * h4.y
                 + wreg[k + 2] * h4.z + wreg[k + 3] * h4.w;
        }
        #pragma unroll
        for (int k = 0; k < 22; k++)
            acc += s_w2t[k * 512 + r] * s_h[64 + k];
        const float* wg = g_whh + r * 128 + 86;
        #pragma unroll
        for (int k = 0; k < 42; k++)
            acc += wg[k] * s_h[86 + k];
        s_g[r] = acc;
        __syncthreads();

        if (r < 128) {
            float ig = 1.f / (1.f + expf(-s_g[r]));
            float fg = 1.f / (1.f + expf(-s_g[128 + r]));
            float gg = tanhf(s_g[256 + r]);
            float og = 1.f / (1.f + expf(-s_g[384 + r]));
            c = fg * c + ig * gg;
            float h = og * tanhf(c);
            s_h[r] = h;
            outs[((long)t * BB + b) * 128 + r] = h;
        }
        __syncthreads();
    }

    if (r < 128) {
        store_out(outbuf, OUT_HF + (long)b * 128 + r, out_elems, s_h[r]);
        store_out(outbuf, OUT_CF + (long)b * 128 + r, out_elems, c);
    }
}

// ---------------------------------------------------------------------------
// Value head: one warp per sample
// ---------------------------------------------------------------------------
__global__ void value_kernel(const void* __restrict__ vw, long vw_n,
                             const void* __restrict__ vb, long vb_n,
                             void* outbuf, long out_elems)
{
    int gw   = (blockIdx.x * blockDim.x + threadIdx.x) >> 5;
    int lane = threadIdx.x & 31;
    if (gw >= TB) return;
    const int bf = g_bf16;
    const float* h = g_sc + S_OUTS + (long)gw * 128;
    float s = 0.f;
    #pragma unroll
    for (int k = lane; k < 128; k += 32) s += h[k] * ldin(vw, k, vw_n, bf);
    #pragma unroll
    for (int off = 16; off; off >>= 1) s += __shfl_xor_sync(0xffffffffu, s, off);
    if (lane == 0)
        store_out(outbuf, OUT_VALUES + gw, out_elems, s + ldin(vb, 0, vb_n, bf));
}

// ---------------------------------------------------------------------------
// Host launcher — static smem only, no cudaFuncSetAttribute anywhere.
// ---------------------------------------------------------------------------
extern "C" void kernel_launch(void* const* d_in, const int* in_sizes, int n_in,
                              void* d_out, int out_size)
{
    static const long WANT[24] = {
        52559872L, 16384L, 16384L, 32768L,
        576L, 32L, 18432L, 64L, 36864L, 64L,
        327680L, 128L, 28928L, 64L, 4096L, 64L,
        98304L, 65536L, 512L, 512L,
        295040L, 2305L, 128L, 1L
    };
    const void* inp[24];
    long        bnd[24];
    {
        int matched = 0;
        static const long SCALES[3] = {1L, 4L, 2L};
        for (int si = 0; si < 3 && !matched; si++) {
            long sc = SCALES[si];
            int used[64] = {0};
            int ok = (n_in >= 24);
            const void* tp[24]; long tb[24];
            if (ok) {
                for (int j = 0; j < 24; j++) {
                    int found = -1;
                    for (int i = 0; i < n_in && i < 64; i++) {
                        if (!used[i] && (long)in_sizes[i] == WANT[j] * sc) { found = i; break; }
                    }
                    if (found < 0) { ok = 0; break; }
                    used[found] = 1;
                    tp[j] = d_in[found];
                    long actual = (long)in_sizes[found];
                    tb[j] = (WANT[j] < actual) ? WANT[j] : actual;
                }
            }
            if (ok) {
                for (int j = 0; j < 24; j++) { inp[j] = tp[j]; bnd[j] = tb[j]; }
                matched = 1;
            }
        }
        if (!matched) {
            for (int j = 0; j < 24; j++) {
                if (j < n_in) {
                    inp[j] = d_in[j];
                    long actual = (long)in_sizes[j];
                    bnd[j] = (WANT[j] < actual) ? WANT[j] : actual;
                } else {
                    inp[j] = d_in[0];
                    bnd[j] = 0;
                }
            }
        }
    }

    const long out_elems = (long)out_size;

    float *scP, *c3P;
    cudaGetSymbolAddress((void**)&scP, g_sc);
    cudaGetSymbolAddress((void**)&c3P, g_c3);

    // 1) single merged prep launch
    prep_kernel<<<64, 256>>>(
        inp[0], bnd[0], inp[3], bnd[3], inp[17], bnd[17],
        inp[4], bnd[4], inp[5], bnd[5],
        inp[6], bnd[6], inp[7], bnd[7],
        inp[8], bnd[8], inp[9], bnd[9]);

    // 2) chunked CNN + fc GEMM -> emb cols 0..127
    for (int ch = 0; ch < NCHUNK; ch++) {
        int base = ch * CHUNK;
        conv_fused_kernel<<<CHUNK, 256>>>(inp[0], bnd[0], c3P, base);
        gemm_bt_kernel<true, false><<<dim3(CHUNK / 64, 2), 256>>>(
            nullptr, 0L, c3P, CNN_FLAT,
            inp[10], bnd[10], inp[11], bnd[11], nullptr, 0L,
            scP + S_EMB + (long)base * 192, 0L, 192, 128, CNN_FLAT,
            d_out, out_elems);
    }

    // 3) Scalar MLP -> emb cols 128..191
    gemm_bt_kernel<true, false><<<dim3(TB / 64, 1), 256>>>(
        inp[0], bnd[0], nullptr, OBS_DIM,
        inp[12], bnd[12], inp[13], bnd[13], nullptr, 0L,
        scP + S_SC1, 0L, 64, 64, SCALAR_D, d_out, out_elems);
    gemm_bt_kernel<true, false><<<dim3(TB / 64, 1), 256>>>(
        nullptr, 0L, scP + S_SC1, 64,
        inp[14], bnd[14], inp[15], bnd[15], nullptr, 0L,
        scP + S_EMB + 128, 0L, 192, 64, 64, d_out, out_elems);

    // 4) LSTM input projection
    gemm_bt_kernel<false, false><<<dim3(TB / 64, 8), 256>>>(
        nullptr, 0L, scP + S_EMB, 192,
        inp[16], bnd[16], inp[18], bnd[18], inp[19], bnd[19],
        scP + S_XW, 0L, 512, 512, 192, d_out, out_elems);

    // 5) Recurrence
    lstm_kernel<<<BB, 512>>>(inp[1], bnd[1], inp[2], bnd[2], d_out, out_elems);

    // 6) Policy head -> logits
    gemm_bt_kernel<false, true><<<dim3(TB / 64, (NACT + 63) / 64), 256>>>(
        nullptr, 0L, scP + S_OUTS, 128,
        inp[20], bnd[20], inp[21], bnd[21], nullptr, 0L,
        nullptr, OUT_LOGITS, NACT, NACT, 128, d_out, out_elems);

    // 7) Value head -> values
    value_kernel<<<TB / 8, 256>>>(inp[22], bnd[22], inp[23], bnd[23],
                                  d_out, out_elems);
}

// round 15
// speedup vs baseline: 1.4732x; 1.0709x over previous
#include <cuda_runtime.h>
#include <cuda_bf16.h>
#include <math.h>
#include <stdint.h>

typedef unsigned long long ull;

// ---------------------------------------------------------------------------
// Problem constants
// ---------------------------------------------------------------------------
#define TT        256
#define BB        128
#define TB        32768            // T*B
#define OBS_DIM   1604
#define SCALAR_D  452
#define HID       128
#define NACT      2305
#define CNN_FLAT  2560
#define CHUNK     4096
#define NCHUNK    8

// d_out layout (elements): logits | values | h_f | c_f
#define OUT_LOGITS 0L
#define OUT_VALUES 75530240L
#define OUT_HF     75563008L
#define OUT_CF     75579392L

// Scratch pool offsets (floats) — static
#define S_SC1     0L              // 32768 x 64
#define S_EMB     2097152L        // 32768 x 192
#define S_XW      8388608L        // 32768 x 512
#define S_OUTS    25165824L       // 32768 x 128
#define SCRATCH   29360128L       // ~117 MB

__device__ float g_sc[SCRATCH];
__device__ float g_c3[(long)CHUNK * CNN_FLAT];   // 4096 x 2560 (~42 MB)
__device__ float g_whh[512 * 128];               // normalized f32 w_hh
__device__ int   g_done[TB];
__device__ int   g_bf16;

// Prepped conv weights (f32; pair-interleaved ull layouts for f32x2)
__device__ float g_w1[576];
__device__ float g_b1[32];
__device__ float g_b2[64];
__device__ float g_b3[64];
__device__ float g_w2p[18432];   // (ib4, pr32, icl8, ky3, k3, o2)
__device__ float g_w3p[36864];   // (ib32, pr32, icl2, ky3, k3, o2)

// ---------------------------------------------------------------------------
// f32x2 packed-math helpers
// ---------------------------------------------------------------------------
__device__ __forceinline__ ull pk2(float a, float b)
{ ull r; asm("mov.b64 %0, {%1, %2};" : "=l"(r) : "f"(a), "f"(b)); return r; }
__device__ __forceinline__ float2 up2(ull v)
{ float2 f; asm("mov.b64 {%0, %1}, %2;" : "=f"(f.x), "=f"(f.y) : "l"(v)); return f; }
__device__ __forceinline__ ull bc2(float v)
{ ull r; asm("mov.b64 %0, {%1, %1};" : "=l"(r) : "f"(v)); return r; }
__device__ __forceinline__ void fma2(ull& d, ull a, ull b)
{ asm("fma.rn.f32x2 %0, %1, %2, %0;" : "+l"(d) : "l"(a), "l"(b)); }

// ---------------------------------------------------------------------------
// Clamped, dtype-dispatched input load
// ---------------------------------------------------------------------------
__device__ __forceinline__ float ldin(const void* p, long i, long n, int bf)
{
    if (n <= 0) return 0.f;
    if (i >= n) i = n - 1;
    if (i < 0) i = 0;
    return bf ? __bfloat162float(((const __nv_bfloat16*)p)[i])
              : ((const float*)p)[i];
}

// ---------------------------------------------------------------------------
// MERGED prep kernel (single launch). Every block independently re-derives
// the dtype flag from the same clamped 4096-word scan of obs, then:
//   block 0: g_bf16 store + done-mask normalize
//   blocks 1..16: w_hh -> f32
//   blocks 17..63: conv weight prep (pair-interleave)
// ---------------------------------------------------------------------------
__global__ void __launch_bounds__(256) prep_kernel(
    const void* __restrict__ obs, long obs_n,
    const void* __restrict__ done, long done_n,
    const void* __restrict__ whh, long whh_n,
    const void* __restrict__ w1, long n1, const void* __restrict__ b1, long nb1,
    const void* __restrict__ w2, long n2, const void* __restrict__ b2, long nb2,
    const void* __restrict__ w3, long n3, const void* __restrict__ b3, long nb3)
{
    __shared__ int s_cnt;
    const int tid = threadIdx.x;
    const int bid = blockIdx.x;

    if (tid == 0) s_cnt = 0;
    __syncthreads();
    long lim = obs_n / 2;
    if (lim > 4096) lim = 4096;
    {
        const unsigned* w = (const unsigned*)obs;
        int c = 0;
        for (long i = tid; i < lim; i += 256) {
            unsigned b1v = (w[i] >> 8) & 0xFF;
            if (b1v >= 0x3A && b1v < 0x40) c++;
        }
        atomicAdd(&s_cnt, c);
    }
    __syncthreads();
    const int bf = (s_cnt > (int)(lim / 2)) ? 1 : 0;

    if (bid == 0) {
        if (tid == 0) g_bf16 = bf;
        __shared__ int s_ni, s_nf, s_nb;
        if (tid == 0) { s_ni = 0; s_nf = 0; s_nb = 0; }
        __syncthreads();
        long scan = done_n / 4;
        if (scan > 8192) scan = 8192;
        const unsigned* w = (const unsigned*)done;
        int ni = 0, nf = 0, nb = 0;
        for (long i = tid; i < scan; i += 256) {
            unsigned v = w[i];
            if (v > 1u) ni = 1;
            if (v != 0u && v != 0x3F800000u) nf = 1;
            unsigned lo = v & 0xFFFFu, hi = v >> 16;
            if ((lo != 0u && lo != 0x3F80u) || (hi != 0u && hi != 0x3F80u)) nb = 1;
        }
        if (ni) atomicOr(&s_ni, 1);
        if (nf) atomicOr(&s_nf, 1);
        if (nb) atomicOr(&s_nb, 1);
        __syncthreads();
        long dl = done_n < TB ? done_n : TB;
        if (!s_ni) {
            const int* p = (const int*)done;
            for (int i = tid; i < TB; i += 256) g_done[i] = (i < dl) ? (p[i] != 0) : 0;
        } else if (!s_nf) {
            const float* p = (const float*)done;
            for (int i = tid; i < TB; i += 256) g_done[i] = (i < dl) ? (p[i] != 0.f) : 0;
        } else if (!s_nb) {
            const unsigned short* p = (const unsigned short*)done;
            for (int i = tid; i < TB; i += 256) g_done[i] = (i < dl) ? (p[i] != 0) : 0;
        } else {
            const unsigned char* p = (const unsigned char*)done;
            for (int i = tid; i < TB; i += 256) g_done[i] = (i < dl) ? (p[i] != 0) : 0;
        }
    } else if (bid <= 16) {
        for (int i = (bid - 1) * 256 + tid; i < 512 * 128; i += 16 * 256)
            g_whh[i] = ldin(whh, i, whh_n, bf);
    } else {
        for (int j = (bid - 17) * 256 + tid; j < 36864; j += 47 * 256) {
            {   // w3p: (ib32, pr32, icl2, ky3, k3, o2)
                int o = j & 1; int t = j >> 1;
                int k = t % 3; t /= 3;
                int ky = t % 3; t /= 3;
                int icl = t & 1; t >>= 1;
                int pr = t & 31; int ib = t >> 5;
                g_w3p[j] = ldin(w3, (long)(pr * 2 + o) * 576 + (ib * 2 + icl) * 9 + ky * 3 + k, n3, bf);
            }
            if (j < 18432) {   // w2p: (ib4, pr32, icl8, ky3, k3, o2)
                int o = j & 1; int t = j >> 1;
                int k = t % 3; t /= 3;
                int ky = t % 3; t /= 3;
                int icl = t & 7; t >>= 3;
                int pr = t & 31; int ib = t >> 5;
                g_w2p[j] = ldin(w2, (long)(pr * 2 + o) * 288 + (ib * 8 + icl) * 9 + ky * 3 + k, n2, bf);
            }
            if (j < 576) g_w1[j] = ldin(w1, j, n1, bf);
            if (j < 32)  g_b1[j] = ldin(b1, j, nb1, bf);
            if (j < 64) { g_b2[j] = ldin(b2, j, nb2, bf); g_b3[j] = ldin(b3, j, nb3, bf); }
        }
    }
}

// ---------------------------------------------------------------------------
// Output store: dtype-dispatched, clamped
// ---------------------------------------------------------------------------
__device__ __forceinline__ void store_out(void* out, long idx, long out_elems, float v)
{
    if (idx >= out_elems || idx < 0) return;
    if (g_bf16) ((__nv_bfloat16*)out)[idx] = __float2bfloat16(v);
    else        ((float*)out)[idx] = v;
}

// ---------------------------------------------------------------------------
// Fused CNN — conflict-free odd pitches, scalar LDS, rolling input windows,
// 3 CTAs/SM. Static smem 46,896 B.
// Phase1 (floats): IN @0 (2*34*21=1428) | C1 @1428 (8*33*21=5544)
//                  | W2 @6972 (4608) | W1 @11580 (144)  -> total 11724
// Phase2:          C2 @0 (64*16*9=9216, scalar, pitch 9)
// ---------------------------------------------------------------------------
#define CV_IN   0
#define CV_C1   1428
#define CV_W2   6972
#define CV_W1   11580
#define CV_C2   0
#define CV_TOT  11724

__global__ void __launch_bounds__(256, 3) conv_fused_kernel(
    const void* __restrict__ obs, long obs_n,
    float* __restrict__ c3out, int base)
{
    __shared__ __align__(16) float sm[CV_TOT];

    const int tid = threadIdx.x;
    const int bf  = g_bf16;
    const int s   = base + blockIdx.x;

    // zero IN + C1 (padding borders persist across ib slices)
    for (int i = tid; i < CV_W2; i += 256) sm[i] = 0.f;
    __syncthreads();

    // obs grid -> padded IN (pitch 21)
    const long gbase = (long)s * OBS_DIM + SCALAR_D;
    for (int i = tid; i < 1152; i += 256) {
        int c = i / 576, r = i % 576;
        int y = r / 18, x = r % 18;
        sm[CV_IN + c * 714 + (y + 1) * 21 + (x + 1)] = ldin(obs, gbase + i, obs_n, bf);
    }

    // conv2 accumulators: thread = (ocg2 0..15 -> 2 oc pairs, y2 0..15)
    const int ocg2 = tid >> 4, y2 = tid & 15;
    ull acc2p[2][9];
    #pragma unroll
    for (int p = 0; p < 2; p++) {
        ull bz = pk2(g_b2[ocg2 * 4 + 2 * p], g_b2[ocg2 * 4 + 2 * p + 1]);
        #pragma unroll
        for (int x = 0; x < 9; x++) acc2p[p][x] = bz;
    }
    const int ocl = tid >> 5, y1 = tid & 31;

    // ---- conv1 (8 oc at a time) + conv2 partial accumulation ----
    for (int ib = 0; ib < 4; ib++) {
        for (int i = tid; i < 144; i += 256) sm[CV_W1 + i] = g_w1[ib * 144 + i];
        for (int i = tid; i < 1152; i += 256)
            ((float4*)(sm + CV_W2))[i] = ((const float4*)(g_w2p + ib * 4608))[i];
        __syncthreads();

        // conv1: one (ocl, y1) per thread, 18 x-outputs, rolling window
        {
            float acc[18];
            float bz = g_b1[ib * 8 + ocl];
            #pragma unroll
            for (int x = 0; x < 18; x++) acc[x] = bz;
            #pragma unroll
            for (int ic = 0; ic < 2; ic++) {
                #pragma unroll
                for (int ky = 0; ky < 3; ky++) {
                    const float* rp = sm + CV_IN + ic * 714 + (y1 + ky) * 21;
                    const float* wp = sm + CV_W1 + (ocl * 2 + ic) * 9 + ky * 3;
                    float w0 = wp[0], wA = wp[1], wB = wp[2];
                    float a0 = rp[0], a1 = rp[1];
                    #pragma unroll
                    for (int x = 0; x < 18; x++) {
                        float a2 = rp[x + 2];
                        acc[x] += w0 * a0 + wA * a1 + wB * a2;
                        a0 = a1; a1 = a2;
                    }
                }
            }
            float* cp = sm + CV_C1 + ocl * 693 + (y1 + 1) * 21;
            #pragma unroll
            for (int x = 0; x < 18; x++) cp[x + 1] = fmaxf(acc[x], 0.f);
        }
        __syncthreads();

        // conv2 partial over this 8-ic slice (f32x2, rolling scalar window)
        #pragma unroll 1
        for (int icl = 0; icl < 8; icl++) {
            #pragma unroll
            for (int ky = 0; ky < 3; ky++) {
                const float* rp = sm + CV_C1 + icl * 693 + (2 * y2 + ky) * 21;
                const ull* wp = (const ull*)(sm + CV_W2);
                int wb0 = ((ocg2 * 2) * 8 + icl) * 9 + ky * 3;
                int wb1 = ((ocg2 * 2 + 1) * 8 + icl) * 9 + ky * 3;
                ull w00 = wp[wb0], w01 = wp[wb0 + 1], w02 = wp[wb0 + 2];
                ull w10 = wp[wb1], w11 = wp[wb1 + 1], w12 = wp[wb1 + 2];
                float a0 = rp[0], a1 = rp[1];
                #pragma unroll
                for (int x = 0; x < 9; x++) {
                    float a2 = rp[2 * x + 2];
                    ull b0 = bc2(a0), b1v = bc2(a1), b2v = bc2(a2);
                    fma2(acc2p[0][x], w00, b0);
                    fma2(acc2p[0][x], w01, b1v);
                    fma2(acc2p[0][x], w02, b2v);
                    fma2(acc2p[1][x], w10, b0);
                    fma2(acc2p[1][x], w11, b1v);
                    fma2(acc2p[1][x], w12, b2v);
                    a0 = a2; a1 = rp[2 * x + 3];
                }
            }
        }
        __syncthreads();
    }

    // write c2 (ReLU, [64][16][9] pitch 9, scalar) over the phase-1 region
    #pragma unroll
    for (int p = 0; p < 2; p++)
        #pragma unroll
        for (int x = 0; x < 9; x++) {
            float2 f = up2(acc2p[p][x]);
            sm[CV_C2 + (ocg2 * 4 + 2 * p + 0) * 144 + y2 * 9 + x] = fmaxf(f.x, 0.f);
            sm[CV_C2 + (ocg2 * 4 + 2 * p + 1) * 144 + y2 * 9 + x] = fmaxf(f.y, 0.f);
        }
    __syncthreads();

    // ---- conv3: thread = (ocg3 0..31 -> 1 oc pair, y3 0..7) ----
    // Weights direct from L1-resident g_w3p; scalar conflict-free c2 reads.
    const int ocg3 = tid >> 3, y3 = tid & 7;
    ull acc3p[5];
    {
        ull bz = pk2(g_b3[ocg3 * 2], g_b3[ocg3 * 2 + 1]);
        #pragma unroll
        for (int x = 0; x < 5; x++) acc3p[x] = bz;
    }

    #pragma unroll 1
    for (int ib = 0; ib < 32; ib++) {
        #pragma unroll
        for (int icl = 0; icl < 2; icl++) {
            int ic = ib * 2 + icl;
            #pragma unroll
            for (int ky = 0; ky < 3; ky++) {
                int row = 2 * y3 + ky - 1;
                const ull* wp = (const ull*)g_w3p +
                                (((long)(ib * 32 + ocg3) * 2 + icl) * 3 + ky) * 3;
                ull w0 = wp[0], wA = wp[1], wB = wp[2];
                float in[11];
                if (row >= 0 && row < 16) {
                    const float* cp = sm + CV_C2 + ic * 144 + row * 9;
                    in[0] = 0.f;
                    #pragma unroll
                    for (int q = 0; q < 9; q++) in[q + 1] = cp[q];
                    in[10] = 0.f;
                } else {
                    #pragma unroll
                    for (int q = 0; q < 11; q++) in[q] = 0.f;
                }
                #pragma unroll
                for (int x = 0; x < 5; x++) {
                    fma2(acc3p[x], w0, bc2(in[2 * x]));
                    fma2(acc3p[x], wA, bc2(in[2 * x + 1]));
                    fma2(acc3p[x], wB, bc2(in[2 * x + 2]));
                }
            }
        }
    }

    float* outp = c3out + (long)blockIdx.x * CNN_FLAT;
    #pragma unroll
    for (int x = 0; x < 5; x++) {
        float2 f = up2(acc3p[x]);
        outp[(long)(ocg3 * 2 + 0) * 40 + y3 * 5 + x] = fmaxf(f.x, 0.f);
        outp[(long)(ocg3 * 2 + 1) * 40 + y3 * 5 + x] = fmaxf(f.y, 0.f);
    }
}

// ---------------------------------------------------------------------------
// Tiled SGEMM with f32x2 microkernel (unchanged from passing R14)
// ---------------------------------------------------------------------------
template <bool RELU, bool TO_OUT>
__global__ void __launch_bounds__(256, 2) gemm_bt_kernel(
    const void* __restrict__ Araw, long a_n,
    const float* __restrict__ Af, long lda,
    const void* __restrict__ B, long b_n,
    const void* __restrict__ bias, long bias_n,
    const void* __restrict__ bias2, long bias2_n,
    float* __restrict__ Cf, long c_off, long ldc, int N, int K,
    void* outbuf, long out_elems)
{
    __shared__ __align__(16) float sA[16][68];
    __shared__ __align__(16) float sB[16][68];

    const int tid = threadIdx.x;
    const int tx = tid & 15, ty = tid >> 4;
    const int m0 = blockIdx.x * 64;
    const int n0 = blockIdx.y * 64;
    const int bf = g_bf16;

    ull accp[4][2] = {};

    for (int k0 = 0; k0 < K; k0 += 16) {
        for (int e = tid; e < 1024; e += 256) {
            int k = e & 15, m = e >> 4;
            int gk = k0 + k;
            float v = 0.f;
            if (gk < K) {
                long ai = (long)(m0 + m) * lda + gk;
                v = Af ? Af[ai] : ldin(Araw, ai, a_n, bf);
            }
            sA[k][m] = v;
        }
        for (int e = tid; e < 1024; e += 256) {
            int k = e & 15, n = e >> 4;
            int gn = n0 + n, gk = k0 + k;
            sB[k][n] = (gn < N && gk < K) ? ldin(B, (long)gn * K + gk, b_n, bf) : 0.f;
        }
        __syncthreads();
        #pragma unroll
        for (int kk = 0; kk < 16; kk++) {
            float4 av = *(const float4*)&sA[kk][ty * 4];
            ull b0 = *(const ull*)&sB[kk][tx * 4];
            ull b1 = *(const ull*)&sB[kk][tx * 4 + 2];
            ull a0 = bc2(av.x), a1 = bc2(av.y), a2 = bc2(av.z), a3 = bc2(av.w);
            fma2(accp[0][0], a0, b0); fma2(accp[0][1], a0, b1);
            fma2(accp[1][0], a1, b0); fma2(accp[1][1], a1, b1);
            fma2(accp[2][0], a2, b0); fma2(accp[2][1], a2, b1);
            fma2(accp[3][0], a3, b0); fma2(accp[3][1], a3, b1);
        }
        __syncthreads();
    }

    #pragma unroll
    for (int i = 0; i < 4; i++) {
        int gm = m0 + ty * 4 + i;
        #pragma unroll
        for (int jp = 0; jp < 2; jp++) {
            float2 f = up2(accp[i][jp]);
            #pragma unroll
            for (int o = 0; o < 2; o++) {
                int gn = n0 + tx * 4 + jp * 2 + o;
                if (gn < N) {
                    float v = o ? f.y : f.x;
                    if (bias)  v += ldin(bias,  gn, bias_n,  bf);
                    if (bias2) v += ldin(bias2, gn, bias2_n, bf);
                    if (RELU) v = fmaxf(v, 0.f);
                    if (TO_OUT) store_out(outbuf, c_off + (long)gm * ldc + gn, out_elems, v);
                    else        Cf[(long)gm * ldc + gn] = v;
                }
            }
        }
    }
}

// ---------------------------------------------------------------------------
// LSTM (unchanged from passing R14)
// ---------------------------------------------------------------------------
#define LW_SM_W2   0
#define LW_SM_H    11264
#define LW_SM_G    11392
#define LW_SM_TOT  11904

__global__ void __launch_bounds__(512) lstm_kernel(
    const void* __restrict__ h0, long h0_n,
    const void* __restrict__ c0, long c0_n,
    void* outbuf, long out_elems)
{
    __shared__ float sm[LW_SM_TOT];
    float* s_w2t = sm + LW_SM_W2;
    float* s_h   = sm + LW_SM_H;
    float* s_g   = sm + LW_SM_G;

    const int b = blockIdx.x;
    const int r = threadIdx.x;
    const int bf = g_bf16;

    const float* xw   = g_sc + S_XW;
    float*       outs = g_sc + S_OUTS;

    float wreg[64];
    #pragma unroll
    for (int k = 0; k < 64; k++) wreg[k] = g_whh[r * 128 + k];
    #pragma unroll
    for (int k = 0; k < 22; k++) s_w2t[k * 512 + r] = g_whh[r * 128 + 64 + k];

    float c = 0.f;
    if (r < 128) {
        s_h[r] = ldin(h0, (long)b * 128 + r, h0_n, bf);
        c      = ldin(c0, (long)b * 128 + r, c0_n, bf);
    }
    __syncthreads();

    for (int t = 0; t < TT; t++) {
        if (r < 128) {
            float keep = (t == 0) ? 1.f : (g_done[(t - 1) * BB + b] ? 0.f : 1.f);
            s_h[r] *= keep;
            c *= keep;
        }
        __syncthreads();

        float acc = xw[((long)t * BB + b) * 512 + r];
        #pragma unroll
        for (int k = 0; k < 64; k += 4) {
            float4 h4 = *(const float4*)&s_h[k];
            acc += wreg[k] * h4.x + wreg[k + 1] * h4.y
                 + wreg[k + 2] * h4.z + wreg[k + 3] * h4.w;
        }
        #pragma unroll
        for (int k = 0; k < 22; k++)
            acc += s_w2t[k * 512 + r] * s_h[64 + k];
        const float* wg = g_whh + r * 128 + 86;
        #pragma unroll
        for (int k = 0; k < 42; k++)
            acc += wg[k] * s_h[86 + k];
        s_g[r] = acc;
        __syncthreads();

        if (r < 128) {
            float ig = 1.f / (1.f + expf(-s_g[r]));
            float fg = 1.f / (1.f + expf(-s_g[128 + r]));
            float gg = tanhf(s_g[256 + r]);
            float og = 1.f / (1.f + expf(-s_g[384 + r]));
            c = fg * c + ig * gg;
            float h = og * tanhf(c);
            s_h[r] = h;
            outs[((long)t * BB + b) * 128 + r] = h;
        }
        __syncthreads();
    }

    if (r < 128) {
        store_out(outbuf, OUT_HF + (long)b * 128 + r, out_elems, s_h[r]);
        store_out(outbuf, OUT_CF + (long)b * 128 + r, out_elems, c);
    }
}

// ---------------------------------------------------------------------------
// Value head: one warp per sample
// ---------------------------------------------------------------------------
__global__ void value_kernel(const void* __restrict__ vw, long vw_n,
                             const void* __restrict__ vb, long vb_n,
                             void* outbuf, long out_elems)
{
    int gw   = (blockIdx.x * blockDim.x + threadIdx.x) >> 5;
    int lane = threadIdx.x & 31;
    if (gw >= TB) return;
    const int bf = g_bf16;
    const float* h = g_sc + S_OUTS + (long)gw * 128;
    float s = 0.f;
    #pragma unroll
    for (int k = lane; k < 128; k += 32) s += h[k] * ldin(vw, k, vw_n, bf);
    #pragma unroll
    for (int off = 16; off; off >>= 1) s += __shfl_xor_sync(0xffffffffu, s, off);
    if (lane == 0)
        store_out(outbuf, OUT_VALUES + gw, out_elems, s + ldin(vb, 0, vb_n, bf));
}

// ---------------------------------------------------------------------------
// Host launcher — static smem only, no cudaFuncSetAttribute anywhere.
// ---------------------------------------------------------------------------
extern "C" void kernel_launch(void* const* d_in, const int* in_sizes, int n_in,
                              void* d_out, int out_size)
{
    static const long WANT[24] = {
        52559872L, 16384L, 16384L, 32768L,
        576L, 32L, 18432L, 64L, 36864L, 64L,
        327680L, 128L, 28928L, 64L, 4096L, 64L,
        98304L, 65536L, 512L, 512L,
        295040L, 2305L, 128L, 1L
    };
    const void* inp[24];
    long        bnd[24];
    {
        int matched = 0;
        static const long SCALES[3] = {1L, 4L, 2L};
        for (int si = 0; si < 3 && !matched; si++) {
            long sc = SCALES[si];
            int used[64] = {0};
            int ok = (n_in >= 24);
            const void* tp[24]; long tb[24];
            if (ok) {
                for (int j = 0; j < 24; j++) {
                    int found = -1;
                    for (int i = 0; i < n_in && i < 64; i++) {
                        if (!used[i] && (long)in_sizes[i] == WANT[j] * sc) { found = i; break; }
                    }
                    if (found < 0) { ok = 0; break; }
                    used[found] = 1;
                    tp[j] = d_in[found];
                    long actual = (long)in_sizes[found];
                    tb[j] = (WANT[j] < actual) ? WANT[j] : actual;
                }
            }
            if (ok) {
                for (int j = 0; j < 24; j++) { inp[j] = tp[j]; bnd[j] = tb[j]; }
                matched = 1;
            }
        }
        if (!matched) {
            for (int j = 0; j < 24; j++) {
                if (j < n_in) {
                    inp[j] = d_in[j];
                    long actual = (long)in_sizes[j];
                    bnd[j] = (WANT[j] < actual) ? WANT[j] : actual;
                } else {
                    inp[j] = d_in[0];
                    bnd[j] = 0;
                }
            }
        }
    }

    const long out_elems = (long)out_size;

    float *scP, *c3P;
    cudaGetSymbolAddress((void**)&scP, g_sc);
    cudaGetSymbolAddress((void**)&c3P, g_c3);

    // 1) single merged prep launch
    prep_kernel<<<64, 256>>>(
        inp[0], bnd[0], inp[3], bnd[3], inp[17], bnd[17],
        inp[4], bnd[4], inp[5], bnd[5],
        inp[6], bnd[6], inp[7], bnd[7],
        inp[8], bnd[8], inp[9], bnd[9]);

    // 2) chunked CNN + fc GEMM -> emb cols 0..127
    for (int ch = 0; ch < NCHUNK; ch++) {
        int base = ch * CHUNK;
        conv_fused_kernel<<<CHUNK, 256>>>(inp[0], bnd[0], c3P, base);
        gemm_bt_kernel<true, false><<<dim3(CHUNK / 64, 2), 256>>>(
            nullptr, 0L, c3P, CNN_FLAT,
            inp[10], bnd[10], inp[11], bnd[11], nullptr, 0L,
            scP + S_EMB + (long)base * 192, 0L, 192, 128, CNN_FLAT,
            d_out, out_elems);
    }

    // 3) Scalar MLP -> emb cols 128..191
    gemm_bt_kernel<true, false><<<dim3(TB / 64, 1), 256>>>(
        inp[0], bnd[0], nullptr, OBS_DIM,
        inp[12], bnd[12], inp[13], bnd[13], nullptr, 0L,
        scP + S_SC1, 0L, 64, 64, SCALAR_D, d_out, out_elems);
    gemm_bt_kernel<true, false><<<dim3(TB / 64, 1), 256>>>(
        nullptr, 0L, scP + S_SC1, 64,
        inp[14], bnd[14], inp[15], bnd[15], nullptr, 0L,
        scP + S_EMB + 128, 0L, 192, 64, 64, d_out, out_elems);

    // 4) LSTM input projection
    gemm_bt_kernel<false, false><<<dim3(TB / 64, 8), 256>>>(
        nullptr, 0L, scP + S_EMB, 192,
        inp[16], bnd[16], inp[18], bnd[18], inp[19], bnd[19],
        scP + S_XW, 0L, 512, 512, 192, d_out, out_elems);

    // 5) Recurrence
    lstm_kernel<<<BB, 512>>>(inp[1], bnd[1], inp[2], bnd[2], d_out, out_elems);

    // 6) Policy head -> logits
    gemm_bt_kernel<false, true><<<dim3(TB / 64, (NACT + 63) / 64), 256>>>(
        nullptr, 0L, scP + S_OUTS, 128,
        inp[20], bnd[20], inp[21], bnd[21], nullptr, 0L,
        nullptr, OUT_LOGITS, NACT, NACT, 128, d_out, out_elems);

    // 7) Value head -> values
    value_kernel<<<TB / 8, 256>>>(inp[22], bnd[22], inp[23], bnd[23],
                                  d_out, out_elems);
}

// round 17
// speedup vs baseline: 1.8828x; 1.2780x over previous
#include <cuda_runtime.h>
#include <cuda_bf16.h>
#include <math.h>
#include <stdint.h>

typedef unsigned long long ull;

// ---------------------------------------------------------------------------
// Problem constants
// ---------------------------------------------------------------------------
#define TT        256
#define BB        128
#define TB        32768            // T*B
#define OBS_DIM   1604
#define SCALAR_D  452
#define HID       128
#define NACT      2305
#define CNN_FLAT  2560
#define CHUNK     8192
#define NCHUNK    4

// d_out layout (elements): logits | values | h_f | c_f
#define OUT_LOGITS 0L
#define OUT_VALUES 75530240L
#define OUT_HF     75563008L
#define OUT_CF     75579392L

// Scratch pool offsets (floats) — static
#define S_SC1     0L              // 32768 x 64
#define S_EMB     2097152L        // 32768 x 192
#define S_XW      8388608L        // 32768 x 512
#define S_OUTS    25165824L       // 32768 x 128
#define SCRATCH   29360128L       // ~117 MB

__device__ float g_sc[SCRATCH];
__device__ float g_c3[(long)CHUNK * CNN_FLAT];   // 8192 x 2560 (~84 MB)
__device__ float g_whh[512 * 128];               // normalized f32 w_hh
__device__ int   g_done[TB];
__device__ int   g_bf16;

// Prepped conv weights (f32; pair-interleaved ull layouts for f32x2)
__device__ float g_w1[576];
__device__ float g_b1[32];
__device__ float g_b2[64];
__device__ float g_b3[64];
__device__ float g_w2p[18432];   // (ib4, pr32, icl8, ky3, k3, o2)
__device__ float g_w3p[36864];   // (ib32, pr32, icl2, ky3, k3, o2)

// ---------------------------------------------------------------------------
// f32x2 packed-math helpers
// ---------------------------------------------------------------------------
__device__ __forceinline__ ull pk2(float a, float b)
{ ull r; asm("mov.b64 %0, {%1, %2};" : "=l"(r) : "f"(a), "f"(b)); return r; }
__device__ __forceinline__ float2 up2(ull v)
{ float2 f; asm("mov.b64 {%0, %1}, %2;" : "=f"(f.x), "=f"(f.y) : "l"(v)); return f; }
__device__ __forceinline__ ull bc2(float v)
{ ull r; asm("mov.b64 %0, {%1, %1};" : "=l"(r) : "f"(v)); return r; }
__device__ __forceinline__ void fma2(ull& d, ull a, ull b)
{ asm("fma.rn.f32x2 %0, %1, %2, %0;" : "+l"(d) : "l"(a), "l"(b)); }

// ---------------------------------------------------------------------------
// Clamped, dtype-dispatched input load
// ---------------------------------------------------------------------------
__device__ __forceinline__ float ldin(const void* p, long i, long n, int bf)
{
    if (n <= 0) return 0.f;
    if (i >= n) i = n - 1;
    if (i < 0) i = 0;
    return bf ? __bfloat162float(((const __nv_bfloat16*)p)[i])
              : ((const float*)p)[i];
}

// ---------------------------------------------------------------------------
// MERGED prep kernel (single launch).
// ---------------------------------------------------------------------------
__global__ void __launch_bounds__(256) prep_kernel(
    const void* __restrict__ obs, long obs_n,
    const void* __restrict__ done, long done_n,
    const void* __restrict__ whh, long whh_n,
    const void* __restrict__ w1, long n1, const void* __restrict__ b1, long nb1,
    const void* __restrict__ w2, long n2, const void* __restrict__ b2, long nb2,
    const void* __restrict__ w3, long n3, const void* __restrict__ b3, long nb3)
{
    __shared__ int s_cnt;
    const int tid = threadIdx.x;
    const int bid = blockIdx.x;

    if (tid == 0) s_cnt = 0;
    __syncthreads();
    long lim = obs_n / 2;
    if (lim > 4096) lim = 4096;
    {
        const unsigned* w = (const unsigned*)obs;
        int c = 0;
        for (long i = tid; i < lim; i += 256) {
            unsigned b1v = (w[i] >> 8) & 0xFF;
            if (b1v >= 0x3A && b1v < 0x40) c++;
        }
        atomicAdd(&s_cnt, c);
    }
    __syncthreads();
    const int bf = (s_cnt > (int)(lim / 2)) ? 1 : 0;

    if (bid == 0) {
        if (tid == 0) g_bf16 = bf;
        __shared__ int s_ni, s_nf, s_nb;
        if (tid == 0) { s_ni = 0; s_nf = 0; s_nb = 0; }
        __syncthreads();
        long scan = done_n / 4;
        if (scan > 8192) scan = 8192;
        const unsigned* w = (const unsigned*)done;
        int ni = 0, nf = 0, nb = 0;
        for (long i = tid; i < scan; i += 256) {
            unsigned v = w[i];
            if (v > 1u) ni = 1;
            if (v != 0u && v != 0x3F800000u) nf = 1;
            unsigned lo = v & 0xFFFFu, hi = v >> 16;
            if ((lo != 0u && lo != 0x3F80u) || (hi != 0u && hi != 0x3F80u)) nb = 1;
        }
        if (ni) atomicOr(&s_ni, 1);
        if (nf) atomicOr(&s_nf, 1);
        if (nb) atomicOr(&s_nb, 1);
        __syncthreads();
        long dl = done_n < TB ? done_n : TB;
        if (!s_ni) {
            const int* p = (const int*)done;
            for (int i = tid; i < TB; i += 256) g_done[i] = (i < dl) ? (p[i] != 0) : 0;
        } else if (!s_nf) {
            const float* p = (const float*)done;
            for (int i = tid; i < TB; i += 256) g_done[i] = (i < dl) ? (p[i] != 0.f) : 0;
        } else if (!s_nb) {
            const unsigned short* p = (const unsigned short*)done;
            for (int i = tid; i < TB; i += 256) g_done[i] = (i < dl) ? (p[i] != 0) : 0;
        } else {
            const unsigned char* p = (const unsigned char*)done;
            for (int i = tid; i < TB; i += 256) g_done[i] = (i < dl) ? (p[i] != 0) : 0;
        }
    } else if (bid <= 16) {
        for (int i = (bid - 1) * 256 + tid; i < 512 * 128; i += 16 * 256)
            g_whh[i] = ldin(whh, i, whh_n, bf);
    } else {
        for (int j = (bid - 17) * 256 + tid; j < 36864; j += 47 * 256) {
            {   // w3p: (ib32, pr32, icl2, ky3, k3, o2)
                int o = j & 1; int t = j >> 1;
                int k = t % 3; t /= 3;
                int ky = t % 3; t /= 3;
                int icl = t & 1; t >>= 1;
                int pr = t & 31; int ib = t >> 5;
                g_w3p[j] = ldin(w3, (long)(pr * 2 + o) * 576 + (ib * 2 + icl) * 9 + ky * 3 + k, n3, bf);
            }
            if (j < 18432) {   // w2p: (ib4, pr32, icl8, ky3, k3, o2)
                int o = j & 1; int t = j >> 1;
                int k = t % 3; t /= 3;
                int ky = t % 3; t /= 3;
                int icl = t & 7; t >>= 3;
                int pr = t & 31; int ib = t >> 5;
                g_w2p[j] = ldin(w2, (long)(pr * 2 + o) * 288 + (ib * 8 + icl) * 9 + ky * 3 + k, n2, bf);
            }
            if (j < 576) g_w1[j] = ldin(w1, j, n1, bf);
            if (j < 32)  g_b1[j] = ldin(b1, j, nb1, bf);
            if (j < 64) { g_b2[j] = ldin(b2, j, nb2, bf); g_b3[j] = ldin(b3, j, nb3, bf); }
        }
    }
}

// ---------------------------------------------------------------------------
// Output store: dtype-dispatched, clamped
// ---------------------------------------------------------------------------
__device__ __forceinline__ void store_out(void* out, long idx, long out_elems, float v)
{
    if (idx >= out_elems || idx < 0) return;
    if (g_bf16) ((__nv_bfloat16*)out)[idx] = __float2bfloat16(v);
    else        ((float*)out)[idx] = v;
}

// ---------------------------------------------------------------------------
// Fused CNN — byte-identical structure to the passing R15 kernel.
// ---------------------------------------------------------------------------
#define CV_IN   0
#define CV_C1   1428
#define CV_W2   6972
#define CV_W1   11580
#define CV_C2   0
#define CV_TOT  11724

__global__ void __launch_bounds__(256, 3) conv_fused_kernel(
    const void* __restrict__ obs, long obs_n,
    float* __restrict__ c3out, int base)
{
    __shared__ __align__(16) float sm[CV_TOT];

    const int tid = threadIdx.x;
    const int bf  = g_bf16;
    const int s   = base + blockIdx.x;

    for (int i = tid; i < CV_W2; i += 256) sm[i] = 0.f;
    __syncthreads();

    const long gbase = (long)s * OBS_DIM + SCALAR_D;
    for (int i = tid; i < 1152; i += 256) {
        int c = i / 576, r = i % 576;
        int y = r / 18, x = r % 18;
        sm[CV_IN + c * 714 + (y + 1) * 21 + (x + 1)] = ldin(obs, gbase + i, obs_n, bf);
    }

    const int ocg2 = tid >> 4, y2 = tid & 15;
    ull acc2p[2][9];
    #pragma unroll
    for (int p = 0; p < 2; p++) {
        ull bz = pk2(g_b2[ocg2 * 4 + 2 * p], g_b2[ocg2 * 4 + 2 * p + 1]);
        #pragma unroll
        for (int x = 0; x < 9; x++) acc2p[p][x] = bz;
    }
    const int ocl = tid >> 5, y1 = tid & 31;

    for (int ib = 0; ib < 4; ib++) {
        for (int i = tid; i < 144; i += 256) sm[CV_W1 + i] = g_w1[ib * 144 + i];
        for (int i = tid; i < 1152; i += 256)
            ((float4*)(sm + CV_W2))[i] = ((const float4*)(g_w2p + ib * 4608))[i];
        __syncthreads();

        {
            float acc[18];
            float bz = g_b1[ib * 8 + ocl];
            #pragma unroll
            for (int x = 0; x < 18; x++) acc[x] = bz;
            #pragma unroll
            for (int ic = 0; ic < 2; ic++) {
                #pragma unroll
                for (int ky = 0; ky < 3; ky++) {
                    const float* rp = sm + CV_IN + ic * 714 + (y1 + ky) * 21;
                    const float* wp = sm + CV_W1 + (ocl * 2 + ic) * 9 + ky * 3;
                    float w0 = wp[0], wA = wp[1], wB = wp[2];
                    float a0 = rp[0], a1 = rp[1];
                    #pragma unroll
                    for (int x = 0; x < 18; x++) {
                        float a2 = rp[x + 2];
                        acc[x] += w0 * a0 + wA * a1 + wB * a2;
                        a0 = a1; a1 = a2;
                    }
                }
            }
            float* cp = sm + CV_C1 + ocl * 693 + (y1 + 1) * 21;
            #pragma unroll
            for (int x = 0; x < 18; x++) cp[x + 1] = fmaxf(acc[x], 0.f);
        }
        __syncthreads();

        #pragma unroll 1
        for (int icl = 0; icl < 8; icl++) {
            #pragma unroll
            for (int ky = 0; ky < 3; ky++) {
                const float* rp = sm + CV_C1 + icl * 693 + (2 * y2 + ky) * 21;
                const ull* wp = (const ull*)(sm + CV_W2);
                int wb0 = ((ocg2 * 2) * 8 + icl) * 9 + ky * 3;
                int wb1 = ((ocg2 * 2 + 1) * 8 + icl) * 9 + ky * 3;
                ull w00 = wp[wb0], w01 = wp[wb0 + 1], w02 = wp[wb0 + 2];
                ull w10 = wp[wb1], w11 = wp[wb1 + 1], w12 = wp[wb1 + 2];
                float a0 = rp[0], a1 = rp[1];
                #pragma unroll
                for (int x = 0; x < 9; x++) {
                    float a2 = rp[2 * x + 2];
                    ull b0 = bc2(a0), b1v = bc2(a1), b2v = bc2(a2);
                    fma2(acc2p[0][x], w00, b0);
                    fma2(acc2p[0][x], w01, b1v);
                    fma2(acc2p[0][x], w02, b2v);
                    fma2(acc2p[1][x], w10, b0);
                    fma2(acc2p[1][x], w11, b1v);
                    fma2(acc2p[1][x], w12, b2v);
                    a0 = a2; a1 = rp[2 * x + 3];
                }
            }
        }
        __syncthreads();
    }

    #pragma unroll
    for (int p = 0; p < 2; p++)
        #pragma unroll
        for (int x = 0; x < 9; x++) {
            float2 f = up2(acc2p[p][x]);
            sm[CV_C2 + (ocg2 * 4 + 2 * p + 0) * 144 + y2 * 9 + x] = fmaxf(f.x, 0.f);
            sm[CV_C2 + (ocg2 * 4 + 2 * p + 1) * 144 + y2 * 9 + x] = fmaxf(f.y, 0.f);
        }
    __syncthreads();

    const int ocg3 = tid >> 3, y3 = tid & 7;
    ull acc3p[5];
    {
        ull bz = pk2(g_b3[ocg3 * 2], g_b3[ocg3 * 2 + 1]);
        #pragma unroll
        for (int x = 0; x < 5; x++) acc3p[x] = bz;
    }

    #pragma unroll 1
    for (int ib = 0; ib < 32; ib++) {
        #pragma unroll
        for (int icl = 0; icl < 2; icl++) {
            int ic = ib * 2 + icl;
            #pragma unroll
            for (int ky = 0; ky < 3; ky++) {
                int row = 2 * y3 + ky - 1;
                const ull* wp = (const ull*)g_w3p +
                                (((long)(ib * 32 + ocg3) * 2 + icl) * 3 + ky) * 3;
                ull w0 = wp[0], wA = wp[1], wB = wp[2];
                float in[11];
                if (row >= 0 && row < 16) {
                    const float* cp = sm + CV_C2 + ic * 144 + row * 9;
                    in[0] = 0.f;
                    #pragma unroll
                    for (int q = 0; q < 9; q++) in[q + 1] = cp[q];
                    in[10] = 0.f;
                } else {
                    #pragma unroll
                    for (int q = 0; q < 11; q++) in[q] = 0.f;
                }
                #pragma unroll
                for (int x = 0; x < 5; x++) {
                    fma2(acc3p[x], w0, bc2(in[2 * x]));
                    fma2(acc3p[x], wA, bc2(in[2 * x + 1]));
                    fma2(acc3p[x], wB, bc2(in[2 * x + 2]));
                }
            }
        }
    }

    float* outp = c3out + (long)blockIdx.x * CNN_FLAT;
    #pragma unroll
    for (int x = 0; x < 5; x++) {
        float2 f = up2(acc3p[x]);
        outp[(long)(ocg3 * 2 + 0) * 40 + y3 * 5 + x] = fmaxf(f.x, 0.f);
        outp[(long)(ocg3 * 2 + 1) * 40 + y3 * 5 + x] = fmaxf(f.y, 0.f);
    }
}

// ---------------------------------------------------------------------------
// Tiled SGEMM with f32x2 microkernel + REGISTER DOUBLE-BUFFER prefetch.
// 4 CTAs/SM for latency hiding. C[M,N] = A*B^T + bias(+bias2), ReLU?
// ---------------------------------------------------------------------------
template <bool RELU, bool TO_OUT>
__global__ void __launch_bounds__(256, 4) gemm_bt_kernel(
    const void* __restrict__ Araw, long a_n,
    const float* __restrict__ Af, long lda,
    const void* __restrict__ B, long b_n,
    const void* __restrict__ bias, long bias_n,
    const void* __restrict__ bias2, long bias2_n,
    float* __restrict__ Cf, long c_off, long ldc, int N, int K,
    void* outbuf, long out_elems)
{
    __shared__ __align__(16) float sA[16][68];
    __shared__ __align__(16) float sB[16][68];

    const int tid = threadIdx.x;
    const int tx = tid & 15, ty = tid >> 4;
    const int m0 = blockIdx.x * 64;
    const int n0 = blockIdx.y * 64;
    const int bf = g_bf16;

    // per-thread load coords (4 elems each for A and B)
    const int lk = tid & 15;        // k within tile
    const int lm = tid >> 4;        // m/n base (stride 16)

    ull accp[4][2] = {};
    float ra[4], rb[4];

    // prefetch first tile
    #pragma unroll
    for (int i = 0; i < 4; i++) {
        int m = lm + 16 * i;
        int gk = lk;
        float v = 0.f;
        if (gk < K) {
            long ai = (long)(m0 + m) * lda + gk;
            v = Af ? Af[ai] : ldin(Araw, ai, a_n, bf);
        }
        ra[i] = v;
        int gn = n0 + m;
        rb[i] = (gn < N && gk < K) ? ldin(B, (long)gn * K + gk, b_n, bf) : 0.f;
    }

    for (int k0 = 0; k0 < K; k0 += 16) {
        // commit prefetched tile to smem
        #pragma unroll
        for (int i = 0; i < 4; i++) {
            sA[lk][lm + 16 * i] = ra[i];
            sB[lk][lm + 16 * i] = rb[i];
        }
        __syncthreads();

        // prefetch next tile while computing
        int kn = k0 + 16;
        if (kn < K) {
            #pragma unroll
            for (int i = 0; i < 4; i++) {
                int m = lm + 16 * i;
                int gk = kn + lk;
                float v = 0.f;
                if (gk < K) {
                    long ai = (long)(m0 + m) * lda + gk;
                    v = Af ? Af[ai] : ldin(Araw, ai, a_n, bf);
                }
                ra[i] = v;
                int gn = n0 + m;
                rb[i] = (gn < N && gk < K) ? ldin(B, (long)gn * K + gk, b_n, bf) : 0.f;
            }
        }

        #pragma unroll
        for (int kk = 0; kk < 16; kk++) {
            float4 av = *(const float4*)&sA[kk][ty * 4];
            ull b0 = *(const ull*)&sB[kk][tx * 4];
            ull b1 = *(const ull*)&sB[kk][tx * 4 + 2];
            ull a0 = bc2(av.x), a1 = bc2(av.y), a2 = bc2(av.z), a3 = bc2(av.w);
            fma2(accp[0][0], a0, b0); fma2(accp[0][1], a0, b1);
            fma2(accp[1][0], a1, b0); fma2(accp[1][1], a1, b1);
            fma2(accp[2][0], a2, b0); fma2(accp[2][1], a2, b1);
            fma2(accp[3][0], a3, b0); fma2(accp[3][1], a3, b1);
        }
        __syncthreads();
    }

    #pragma unroll
    for (int i = 0; i < 4; i++) {
        int gm = m0 + ty * 4 + i;
        #pragma unroll
        for (int jp = 0; jp < 2; jp++) {
            float2 f = up2(accp[i][jp]);
            #pragma unroll
            for (int o = 0; o < 2; o++) {
                int gn = n0 + tx * 4 + jp * 2 + o;
                if (gn < N) {
                    float v = o ? f.y : f.x;
                    if (bias)  v += ldin(bias,  gn, bias_n,  bf);
                    if (bias2) v += ldin(bias2, gn, bias2_n, bf);
                    if (RELU) v = fmaxf(v, 0.f);
                    if (TO_OUT) store_out(outbuf, c_off + (long)gm * ldc + gn, out_elems, v);
                    else        Cf[(long)gm * ldc + gn] = v;
                }
            }
        }
    }
}

// ---------------------------------------------------------------------------
// LSTM (unchanged from passing R15)
// ---------------------------------------------------------------------------
#define LW_SM_W2   0
#define LW_SM_H    11264
#define LW_SM_G    11392
#define LW_SM_TOT  11904

__global__ void __launch_bounds__(512) lstm_kernel(
    const void* __restrict__ h0, long h0_n,
    const void* __restrict__ c0, long c0_n,
    void* outbuf, long out_elems)
{
    __shared__ float sm[LW_SM_TOT];
    float* s_w2t = sm + LW_SM_W2;
    float* s_h   = sm + LW_SM_H;
    float* s_g   = sm + LW_SM_G;

    const int b = blockIdx.x;
    const int r = threadIdx.x;
    const int bf = g_bf16;

    const float* xw   = g_sc + S_XW;
    float*       outs = g_sc + S_OUTS;

    float wreg[64];
    #pragma unroll
    for (int k = 0; k < 64; k++) wreg[k] = g_whh[r * 128 + k];
    #pragma unroll
    for (int k = 0; k < 22; k++) s_w2t[k * 512 + r] = g_whh[r * 128 + 64 + k];

    float c = 0.f;
    if (r < 128) {
        s_h[r] = ldin(h0, (long)b * 128 + r, h0_n, bf);
        c      = ldin(c0, (long)b * 128 + r, c0_n, bf);
    }
    __syncthreads();

    for (int t = 0; t < TT; t++) {
        if (r < 128) {
            float keep = (t == 0) ? 1.f : (g_done[(t - 1) * BB + b] ? 0.f : 1.f);
            s_h[r] *= keep;
            c *= keep;
        }
        __syncthreads();

        float acc = xw[((long)t * BB + b) * 512 + r];
        #pragma unroll
        for (int k = 0; k < 64; k += 4) {
            float4 h4 = *(const float4*)&s_h[k];
            acc += wreg[k] * h4.x + wreg[k + 1] * h4.y
                 + wreg[k + 2] * h4.z + wreg[k + 3] * h4.w;
        }
        #pragma unroll
        for (int k = 0; k < 22; k++)
            acc += s_w2t[k * 512 + r] * s_h[64 + k];
        const float* wg = g_whh + r * 128 + 86;
        #pragma unroll
        for (int k = 0; k < 42; k++)
            acc += wg[k] * s_h[86 + k];
        s_g[r] = acc;
        __syncthreads();

        if (r < 128) {
            float ig = 1.f / (1.f + expf(-s_g[r]));
            float fg = 1.f / (1.f + expf(-s_g[128 + r]));
            float gg = tanhf(s_g[256 + r]);
            float og = 1.f / (1.f + expf(-s_g[384 + r]));
            c = fg * c + ig * gg;
            float h = og * tanhf(c);
            s_h[r] = h;
            outs[((long)t * BB + b) * 128 + r] = h;
        }
        __syncthreads();
    }

    if (r < 128) {
        store_out(outbuf, OUT_HF + (long)b * 128 + r, out_elems, s_h[r]);
        store_out(outbuf, OUT_CF + (long)b * 128 + r, out_elems, c);
    }
}

// ---------------------------------------------------------------------------
// Value head: one warp per sample
// ---------------------------------------------------------------------------
__global__ void value_kernel(const void* __restrict__ vw, long vw_n,
                             const void* __restrict__ vb, long vb_n,
                             void* outbuf, long out_elems)
{
    int gw   = (blockIdx.x * blockDim.x + threadIdx.x) >> 5;
    int lane = threadIdx.x & 31;
    if (gw >= TB) return;
    const int bf = g_bf16;
    const float* h = g_sc + S_OUTS + (long)gw * 128;
    float s = 0.f;
    #pragma unroll
    for (int k = lane; k < 128; k += 32) s += h[k] * ldin(vw, k, vw_n, bf);
    #pragma unroll
    for (int off = 16; off; off >>= 1) s += __shfl_xor_sync(0xffffffffu, s, off);
    if (lane == 0)
        store_out(outbuf, OUT_VALUES + gw, out_elems, s + ldin(vb, 0, vb_n, bf));
}

// ---------------------------------------------------------------------------
// Host launcher — static smem only, no cudaFuncSetAttribute anywhere.
// ---------------------------------------------------------------------------
extern "C" void kernel_launch(void* const* d_in, const int* in_sizes, int n_in,
                              void* d_out, int out_size)
{
    static const long WANT[24] = {
        52559872L, 16384L, 16384L, 32768L,
        576L, 32L, 18432L, 64L, 36864L, 64L,
        327680L, 128L, 28928L, 64L, 4096L, 64L,
        98304L, 65536L, 512L, 512L,
        295040L, 2305L, 128L, 1L
    };
    const void* inp[24];
    long        bnd[24];
    {
        int matched = 0;
        static const long SCALES[3] = {1L, 4L, 2L};
        for (int si = 0; si < 3 && !matched; si++) {
            long sc = SCALES[si];
            int used[64] = {0};
            int ok = (n_in >= 24);
            const void* tp[24]; long tb[24];
            if (ok) {
                for (int j = 0; j < 24; j++) {
                    int found = -1;
                    for (int i = 0; i < n_in && i < 64; i++) {
                        if (!used[i] && (long)in_sizes[i] == WANT[j] * sc) { found = i; break; }
                    }
                    if (found < 0) { ok = 0; break; }
                    used[found] = 1;
                    tp[j] = d_in[found];
                    long actual = (long)in_sizes[found];
                    tb[j] = (WANT[j] < actual) ? WANT[j] : actual;
                }
            }
            if (ok) {
                for (int j = 0; j < 24; j++) { inp[j] = tp[j]; bnd[j] = tb[j]; }
                matched = 1;
            }
        }
        if (!matched) {
            for (int j = 0; j < 24; j++) {
                if (j < n_in) {
                    inp[j] = d_in[j];
                    long actual = (long)in_sizes[j];
                    bnd[j] = (WANT[j] < actual) ? WANT[j] : actual;
                } else {
                    inp[j] = d_in[0];
                    bnd[j] = 0;
                }
            }
        }
    }

    const long out_elems = (long)out_size;

    float *scP, *c3P;
    cudaGetSymbolAddress((void**)&scP, g_sc);
    cudaGetSymbolAddress((void**)&c3P, g_c3);

    // 1) single merged prep launch
    prep_kernel<<<64, 256>>>(
        inp[0], bnd[0], inp[3], bnd[3], inp[17], bnd[17],
        inp[4], bnd[4], inp[5], bnd[5],
        inp[6], bnd[6], inp[7], bnd[7],
        inp[8], bnd[8], inp[9], bnd[9]);

    // 2) chunked CNN + fc GEMM -> emb cols 0..127
    for (int ch = 0; ch < NCHUNK; ch++) {
        int base = ch * CHUNK;
        conv_fused_kernel<<<CHUNK, 256>>>(inp[0], bnd[0], c3P, base);
        gemm_bt_kernel<true, false><<<dim3(CHUNK / 64, 2), 256>>>(
            nullptr, 0L, c3P, CNN_FLAT,
            inp[10], bnd[10], inp[11], bnd[11], nullptr, 0L,
            scP + S_EMB + (long)base * 192, 0L, 192, 128, CNN_FLAT,
            d_out, out_elems);
    }

    // 3) Scalar MLP -> emb cols 128..191
    gemm_bt_kernel<true, false><<<dim3(TB / 64, 1), 256>>>(
        inp[0], bnd[0], nullptr, OBS_DIM,
        inp[12], bnd[12], inp[13], bnd[13], nullptr, 0L,
        scP + S_SC1, 0L, 64, 64, SCALAR_D, d_out, out_elems);
    gemm_bt_kernel<true, false><<<dim3(TB / 64, 1), 256>>>(
        nullptr, 0L, scP + S_SC1, 64,
        inp[14], bnd[14], inp[15], bnd[15], nullptr, 0L,
        scP + S_EMB + 128, 0L, 192, 64, 64, d_out, out_elems);

    // 4) LSTM input projection
    gemm_bt_kernel<false, false><<<dim3(TB / 64, 8), 256>>>(
        nullptr, 0L, scP + S_EMB, 192,
        inp[16], bnd[16], inp[18], bnd[18], inp[19], bnd[19],
        scP + S_XW, 0L, 512, 512, 192, d_out, out_elems);

    // 5) Recurrence
    lstm_kernel<<<BB, 512>>>(inp[1], bnd[1], inp[2], bnd[2], d_out, out_elems);

    // 6) Policy head -> logits
    gemm_bt_kernel<false, true><<<dim3(TB / 64, (NACT + 63) / 64), 256>>>(
        nullptr, 0L, scP + S_OUTS, 128,
        inp[20], bnd[20], inp[21], bnd[21], nullptr, 0L,
        nullptr, OUT_LOGITS, NACT, NACT, 128, d_out, out_elems);

    // 7) Value head -> values
    value_kernel<<<TB / 8, 256>>>(inp[22], bnd[22], inp[23], bnd[23],
                                  d_out, out_elems);
}